// round 2
// baseline (speedup 1.0000x reference)
#include <cuda_runtime.h>
#include <math.h>

#define B_    4
#define N_    1024
#define DIM_  1024
#define H_    16
#define HD_   64
#define ROWS_ (B_ * N_)          // 4096
#define SP_   65                 // smem row pitch (floats) to dodge bank conflicts

// Scratch (device globals: allocation-free rule)
__device__ float g_qkv[(size_t)ROWS_ * 3 * DIM_];   // [4096][3072] : q|k|v per token
__device__ float g_attn[(size_t)ROWS_ * DIM_];      // [4096][1024] : attention output

// ---------------------------------------------------------------------------
// C[m,n] = sum_k A[m,k] * Bm[n,k]  (+ bias[n])    A:[M,K] Bm:[N,K] row-major
// 128x128 block tile, BK=8, 256 threads, 8x8 per thread.
// ---------------------------------------------------------------------------
__global__ __launch_bounds__(256) void sgemm_tn(
    const float* __restrict__ A, const float* __restrict__ Bm,
    const float* __restrict__ bias, float* __restrict__ C,
    int M, int N, int K)
{
    __shared__ float As[8][128];
    __shared__ float Bs[8][128];

    int tid = threadIdx.x;
    int bm = blockIdx.y * 128;
    int bn = blockIdx.x * 128;
    int ty = tid >> 4;           // 0..15
    int tx = tid & 15;           // 0..15

    int arow = tid >> 1;         // 0..127
    int aseg = (tid & 1) * 4;    // 0 or 4
    const float* Ap = A + (size_t)(bm + arow) * K + aseg;
    const float* Bp = Bm + (size_t)(bn + arow) * K + aseg;

    float acc[8][8];
#pragma unroll
    for (int i = 0; i < 8; i++)
#pragma unroll
        for (int j = 0; j < 8; j++) acc[i][j] = 0.f;

    for (int k0 = 0; k0 < K; k0 += 8) {
        float4 av = *(const float4*)(Ap + k0);
        float4 bv = *(const float4*)(Bp + k0);
        __syncthreads();
        As[aseg + 0][arow] = av.x; As[aseg + 1][arow] = av.y;
        As[aseg + 2][arow] = av.z; As[aseg + 3][arow] = av.w;
        Bs[aseg + 0][arow] = bv.x; Bs[aseg + 1][arow] = bv.y;
        Bs[aseg + 2][arow] = bv.z; Bs[aseg + 3][arow] = bv.w;
        __syncthreads();
#pragma unroll
        for (int k = 0; k < 8; k++) {
            float a[8], b[8];
            *(float4*)(a)     = *(const float4*)&As[k][ty * 8];
            *(float4*)(a + 4) = *(const float4*)&As[k][ty * 8 + 4];
            *(float4*)(b)     = *(const float4*)&Bs[k][tx * 8];
            *(float4*)(b + 4) = *(const float4*)&Bs[k][tx * 8 + 4];
#pragma unroll
            for (int i = 0; i < 8; i++)
#pragma unroll
                for (int j = 0; j < 8; j++)
                    acc[i][j] = fmaf(a[i], b[j], acc[i][j]);
        }
    }

    int crow = bm + ty * 8;
    int ccol = bn + tx * 8;
    float bq[8];
    if (bias) {
        *(float4*)(bq)     = *(const float4*)(bias + ccol);
        *(float4*)(bq + 4) = *(const float4*)(bias + ccol + 4);
    } else {
#pragma unroll
        for (int j = 0; j < 8; j++) bq[j] = 0.f;
    }
#pragma unroll
    for (int i = 0; i < 8; i++) {
        float4 v0, v1;
        v0.x = acc[i][0] + bq[0]; v0.y = acc[i][1] + bq[1];
        v0.z = acc[i][2] + bq[2]; v0.w = acc[i][3] + bq[3];
        v1.x = acc[i][4] + bq[4]; v1.y = acc[i][5] + bq[5];
        v1.z = acc[i][6] + bq[6]; v1.w = acc[i][7] + bq[7];
        *(float4*)(C + (size_t)(crow + i) * N + ccol)     = v0;
        *(float4*)(C + (size_t)(crow + i) * N + ccol + 4) = v1;
    }
}

// ---------------------------------------------------------------------------
// Fused causal attention with relative position (Music-Transformer skew).
// score[n,m] = (q_n . k_m + q_n . Er[N-1-(n-m)]) * scale, m <= n.
// Block: 64 query rows (n0..n0+63), stream key blocks of 64. Online softmax.
// Threads: 256 as 16x16 grid, each owns a 4x4 score/output micro-tile.
// ---------------------------------------------------------------------------
__global__ __launch_bounds__(256, 2) void attn_fused(const float* __restrict__ Er)
{
    extern __shared__ float sm[];
    float* Qs = sm;                 // 64  x SP_
    float* Ks = Qs + 64 * SP_;      // 64  x SP_
    float* Vs = Ks + 64 * SP_;      // 64  x SP_
    float* Es = Vs + 64 * SP_;      // 127 x SP_  (reused as Ps: 64 x SP_)

    int tid = threadIdx.x;
    int n0 = blockIdx.x * 64;
    int bh = blockIdx.y;
    int b = bh >> 4, h = bh & 15;

    int ty = tid >> 4, tx = tid & 15;
    int r0 = ty * 4, c0 = tx * 4;

    const float* baseq = g_qkv + (size_t)b * N_ * (3 * DIM_) + h * HD_;

    // Load Q tile (64 x 64)
#pragma unroll
    for (int p = 0; p < 4; p++) {
        int row = p * 16 + ty;
        float4 v = *(const float4*)(baseq + (size_t)(n0 + row) * (3 * DIM_) + tx * 4);
        float* d = &Qs[row * SP_ + tx * 4];
        d[0] = v.x; d[1] = v.y; d[2] = v.z; d[3] = v.w;
    }

    float Mx[4], Lx[4], O[4][4];
#pragma unroll
    for (int i = 0; i < 4; i++) {
        Mx[i] = -3.0e38f; Lx[i] = 0.f;
        O[i][0] = O[i][1] = O[i][2] = O[i][3] = 0.f;
    }

    const float scale = 0.125f;   // 64^-0.5

    for (int m0 = 0; m0 <= n0; m0 += 64) {
        __syncthreads();   // protect Vs/Ps reads of previous iteration

        // Load K and V tiles (64 x 64 each)
#pragma unroll
        for (int p = 0; p < 4; p++) {
            int row = p * 16 + ty;
            const float* ksrc = baseq + DIM_ + (size_t)(m0 + row) * (3 * DIM_) + tx * 4;
            float4 kv = *(const float4*)(ksrc);
            float4 vv = *(const float4*)(ksrc + DIM_);
            float* kd = &Ks[row * SP_ + tx * 4];
            kd[0] = kv.x; kd[1] = kv.y; kd[2] = kv.z; kd[3] = kv.w;
            float* vd = &Vs[row * SP_ + tx * 4];
            vd[0] = vv.x; vd[1] = vv.y; vd[2] = vv.z; vd[3] = vv.w;
        }
        // Load Er band: rows ebase..ebase+126 ; Er index = ebase + (c - r + 63)
        int ebase = N_ - 64 - n0 + m0;   // >= 0 always
#pragma unroll
        for (int p = 0; p < 8; p++) {
            int u = p * 16 + ty;
            if (u < 127) {
                int er = ebase + u;
                if (er > N_ - 1) er = N_ - 1;   // only masked entries ever clamp
                float4 ev = *(const float4*)(Er + (size_t)er * HD_ + tx * 4);
                float* ed = &Es[u * SP_ + tx * 4];
                ed[0] = ev.x; ed[1] = ev.y; ed[2] = ev.z; ed[3] = ev.w;
            }
        }
        __syncthreads();

        // Scores: S[i][j] = sum_d Q[r0+i][d] * (K[c0+j][d] + E[c0+j - r0-i + 63][d])
        float S[4][4];
#pragma unroll
        for (int i = 0; i < 4; i++)
#pragma unroll
            for (int j = 0; j < 4; j++) S[i][j] = 0.f;

        int eo = c0 - r0 + 60;   // base E-row for (j - i) in [-3, 3]
#pragma unroll 8
        for (int d = 0; d < 64; d++) {
            float a0 = Qs[(r0 + 0) * SP_ + d];
            float a1 = Qs[(r0 + 1) * SP_ + d];
            float a2 = Qs[(r0 + 2) * SP_ + d];
            float a3 = Qs[(r0 + 3) * SP_ + d];
            float k0 = Ks[(c0 + 0) * SP_ + d];
            float k1 = Ks[(c0 + 1) * SP_ + d];
            float k2 = Ks[(c0 + 2) * SP_ + d];
            float k3 = Ks[(c0 + 3) * SP_ + d];
            float e[7];
#pragma unroll
            for (int t = 0; t < 7; t++) e[t] = Es[(eo + t) * SP_ + d];

            S[0][0] = fmaf(a0, k0 + e[3], S[0][0]);
            S[0][1] = fmaf(a0, k1 + e[4], S[0][1]);
            S[0][2] = fmaf(a0, k2 + e[5], S[0][2]);
            S[0][3] = fmaf(a0, k3 + e[6], S[0][3]);
            S[1][0] = fmaf(a1, k0 + e[2], S[1][0]);
            S[1][1] = fmaf(a1, k1 + e[3], S[1][1]);
            S[1][2] = fmaf(a1, k2 + e[4], S[1][2]);
            S[1][3] = fmaf(a1, k3 + e[5], S[1][3]);
            S[2][0] = fmaf(a2, k0 + e[1], S[2][0]);
            S[2][1] = fmaf(a2, k1 + e[2], S[2][1]);
            S[2][2] = fmaf(a2, k2 + e[3], S[2][2]);
            S[2][3] = fmaf(a2, k3 + e[4], S[2][3]);
            S[3][0] = fmaf(a3, k0 + e[0], S[3][0]);
            S[3][1] = fmaf(a3, k1 + e[1], S[3][1]);
            S[3][2] = fmaf(a3, k2 + e[2], S[3][2]);
            S[3][3] = fmaf(a3, k3 + e[3], S[3][3]);
        }

        // scale + causal mask (only diagonal block has masked entries)
        bool diag = (m0 == n0);
#pragma unroll
        for (int i = 0; i < 4; i++)
#pragma unroll
            for (int j = 0; j < 4; j++) {
                float s = S[i][j] * scale;
                if (diag && (c0 + j > r0 + i)) s = -1.0e30f;
                S[i][j] = s;
            }

        // Online softmax per row; row spread over 16 lanes (width-16 shuffles)
#pragma unroll
        for (int i = 0; i < 4; i++) {
            float rm = fmaxf(fmaxf(S[i][0], S[i][1]), fmaxf(S[i][2], S[i][3]));
            rm = fmaxf(rm, __shfl_xor_sync(0xffffffffu, rm, 1, 16));
            rm = fmaxf(rm, __shfl_xor_sync(0xffffffffu, rm, 2, 16));
            rm = fmaxf(rm, __shfl_xor_sync(0xffffffffu, rm, 4, 16));
            rm = fmaxf(rm, __shfl_xor_sync(0xffffffffu, rm, 8, 16));
            float mn = fmaxf(Mx[i], rm);
            float al = __expf(Mx[i] - mn);
            float rs = 0.f;
#pragma unroll
            for (int j = 0; j < 4; j++) {
                float pv = __expf(S[i][j] - mn);
                S[i][j] = pv;
                rs += pv;
            }
            rs += __shfl_xor_sync(0xffffffffu, rs, 1, 16);
            rs += __shfl_xor_sync(0xffffffffu, rs, 2, 16);
            rs += __shfl_xor_sync(0xffffffffu, rs, 4, 16);
            rs += __shfl_xor_sync(0xffffffffu, rs, 8, 16);
            Lx[i] = Lx[i] * al + rs;
            Mx[i] = mn;
            O[i][0] *= al; O[i][1] *= al; O[i][2] *= al; O[i][3] *= al;
        }

        __syncthreads();            // everyone done reading Es
        float* Ps = Es;             // reuse as P tile (64 x SP_)
#pragma unroll
        for (int i = 0; i < 4; i++)
#pragma unroll
            for (int j = 0; j < 4; j++)
                Ps[(r0 + i) * SP_ + c0 + j] = S[i][j];
        __syncthreads();

        // O[i][j] += sum_c P[r0+i][c] * V[c][c0+j]
#pragma unroll 8
        for (int c = 0; c < 64; c++) {
            float p0 = Ps[(r0 + 0) * SP_ + c];
            float p1 = Ps[(r0 + 1) * SP_ + c];
            float p2 = Ps[(r0 + 2) * SP_ + c];
            float p3 = Ps[(r0 + 3) * SP_ + c];
            float v0 = Vs[c * SP_ + c0 + 0];
            float v1 = Vs[c * SP_ + c0 + 1];
            float v2 = Vs[c * SP_ + c0 + 2];
            float v3 = Vs[c * SP_ + c0 + 3];
            O[0][0] = fmaf(p0, v0, O[0][0]); O[0][1] = fmaf(p0, v1, O[0][1]);
            O[0][2] = fmaf(p0, v2, O[0][2]); O[0][3] = fmaf(p0, v3, O[0][3]);
            O[1][0] = fmaf(p1, v0, O[1][0]); O[1][1] = fmaf(p1, v1, O[1][1]);
            O[1][2] = fmaf(p1, v2, O[1][2]); O[1][3] = fmaf(p1, v3, O[1][3]);
            O[2][0] = fmaf(p2, v0, O[2][0]); O[2][1] = fmaf(p2, v1, O[2][1]);
            O[2][2] = fmaf(p2, v2, O[2][2]); O[2][3] = fmaf(p2, v3, O[2][3]);
            O[3][0] = fmaf(p3, v0, O[3][0]); O[3][1] = fmaf(p3, v1, O[3][1]);
            O[3][2] = fmaf(p3, v2, O[3][2]); O[3][3] = fmaf(p3, v3, O[3][3]);
        }
    }

    // Normalize and write attention output: [b, n, h*64 + d]
    float* op = g_attn + ((size_t)b * N_ + n0) * DIM_ + h * HD_;
#pragma unroll
    for (int i = 0; i < 4; i++) {
        float inv = 1.0f / Lx[i];
        float4 v;
        v.x = O[i][0] * inv; v.y = O[i][1] * inv;
        v.z = O[i][2] * inv; v.w = O[i][3] * inv;
        *(float4*)(op + (size_t)(r0 + i) * DIM_ + c0) = v;
    }
}

// ---------------------------------------------------------------------------
extern "C" void kernel_launch(void* const* d_in, const int* in_sizes, int n_in,
                              void* d_out, int out_size)
{
    const float* x      = (const float*)d_in[0];
    const float* W_qkv  = (const float*)d_in[1];
    const float* W_proj = (const float*)d_in[2];
    const float* b_proj = (const float*)d_in[3];
    const float* Er     = (const float*)d_in[4];
    float* out = (float*)d_out;

    float *qkv, *attn;
    cudaGetSymbolAddress((void**)&qkv, g_qkv);
    cudaGetSymbolAddress((void**)&attn, g_attn);

    int smem = (64 * 3 + 127) * SP_ * (int)sizeof(float);   // ~81 KB
    cudaFuncSetAttribute(attn_fused, cudaFuncAttributeMaxDynamicSharedMemorySize, smem);

    // 1) QKV projection: [4096,1024] @ [3072,1024]^T -> [4096,3072]
    sgemm_tn<<<dim3(3 * DIM_ / 128, ROWS_ / 128), 256>>>(
        x, W_qkv, nullptr, qkv, ROWS_, 3 * DIM_, DIM_);

    // 2) Fused causal relative attention -> g_attn [4096,1024]
    attn_fused<<<dim3(N_ / 64, B_ * H_), 256, smem>>>(Er);

    // 3) Output projection + bias: [4096,1024] @ [1024,1024]^T -> out
    sgemm_tn<<<dim3(DIM_ / 128, ROWS_ / 128), 256>>>(
        attn, W_proj, b_proj, out, ROWS_, DIM_, DIM_);
}

// round 7
// speedup vs baseline: 1.6421x; 1.6421x over previous
#include <cuda_runtime.h>
#include <cuda_bf16.h>
#include <math.h>
#include <stdint.h>

#define B_    4
#define N_    1024
#define DIM_  1024
#define H_    16
#define HD_   64
#define ROWS_ (B_ * N_)          // 4096
#define SP_   65                 // attn smem row pitch (floats)

// ---------------------------------------------------------------------------
// Scratch (device globals: allocation-free rule)
// ---------------------------------------------------------------------------
__device__ float g_qkv[(size_t)ROWS_ * 3 * DIM_];   // [4096][3072]
__device__ float g_attn[(size_t)ROWS_ * DIM_];      // [4096][1024]
__device__ __nv_bfloat16 g_ah[(size_t)ROWS_ * DIM_];       // x / attn hi (reused)
__device__ __nv_bfloat16 g_al[(size_t)ROWS_ * DIM_];       // x / attn lo
__device__ __nv_bfloat16 g_wh[(size_t)3 * DIM_ * DIM_];    // W_qkv hi
__device__ __nv_bfloat16 g_wl[(size_t)3 * DIM_ * DIM_];    // W_qkv lo
__device__ __nv_bfloat16 g_ph[(size_t)DIM_ * DIM_];        // W_proj hi
__device__ __nv_bfloat16 g_pl[(size_t)DIM_ * DIM_];        // W_proj lo

// ---------------------------------------------------------------------------
// Portable PTX helpers (sm_80+ family-generic: ldmatrix / mma.sync / cp.async)
// ---------------------------------------------------------------------------
__device__ __forceinline__ uint32_t smem_u32(const void* p) {
    uint32_t a;
    asm("{ .reg .u64 t; cvta.to.shared.u64 t, %1; cvt.u32.u64 %0, t; }"
        : "=r"(a) : "l"(p));
    return a;
}

#define CP_ASYNC16(saddr, gptr) \
    asm volatile("cp.async.cg.shared.global [%0], [%1], 16;" \
        :: "r"(saddr), "l"(gptr) : "memory")
#define CP_COMMIT() asm volatile("cp.async.commit_group;" ::: "memory")
#define CP_WAIT1()  asm volatile("cp.async.wait_group 1;" ::: "memory")
#define CP_WAIT0()  asm volatile("cp.async.wait_group 0;" ::: "memory")

#define LDSM4(r, addr) \
    asm volatile("ldmatrix.sync.aligned.m8n8.x4.shared.b16 {%0,%1,%2,%3}, [%4];" \
        : "=r"((r)[0]), "=r"((r)[1]), "=r"((r)[2]), "=r"((r)[3]) : "r"(addr))

#define MMA16816(d, a, b0, b1) \
    asm volatile("mma.sync.aligned.m16n8k16.row.col.f32.bf16.bf16.f32 " \
        "{%0,%1,%2,%3}, {%4,%5,%6,%7}, {%8,%9}, {%0,%1,%2,%3};" \
        : "+f"((d)[0]), "+f"((d)[1]), "+f"((d)[2]), "+f"((d)[3]) \
        : "r"((a)[0]), "r"((a)[1]), "r"((a)[2]), "r"((a)[3]), \
          "r"(b0), "r"(b1))

// swizzle: 16B chunk index within a 128B row XORed with row%8
#define SW128(off) ((off) ^ (((off) >> 3) & 0x70))

// ---------------------------------------------------------------------------
// fp32 -> (bf16 hi, bf16 lo) split conversion
// ---------------------------------------------------------------------------
__global__ __launch_bounds__(256) void split_bf16(
    const float* __restrict__ in, __nv_bfloat16* __restrict__ hi,
    __nv_bfloat16* __restrict__ lo, int n)
{
    int i = (blockIdx.x * 256 + threadIdx.x) * 4;
    if (i >= n) return;
    float4 v = *(const float4*)(in + i);
    __nv_bfloat16 h0 = __float2bfloat16(v.x);
    __nv_bfloat16 h1 = __float2bfloat16(v.y);
    __nv_bfloat16 h2 = __float2bfloat16(v.z);
    __nv_bfloat16 h3 = __float2bfloat16(v.w);
    __nv_bfloat16 l0 = __float2bfloat16(v.x - __bfloat162float(h0));
    __nv_bfloat16 l1 = __float2bfloat16(v.y - __bfloat162float(h1));
    __nv_bfloat16 l2 = __float2bfloat16(v.z - __bfloat162float(h2));
    __nv_bfloat16 l3 = __float2bfloat16(v.w - __bfloat162float(h3));
    ((__nv_bfloat162*)(hi + i))[0] = __nv_bfloat162(h0, h1);
    ((__nv_bfloat162*)(hi + i))[1] = __nv_bfloat162(h2, h3);
    ((__nv_bfloat162*)(lo + i))[0] = __nv_bfloat162(l0, l1);
    ((__nv_bfloat162*)(lo + i))[1] = __nv_bfloat162(l2, l3);
}

// ---------------------------------------------------------------------------
// bf16-split GEMM on mma.sync (HMMA): C[m,n] = sum_k A[m,k]*Bm[n,k] (+bias[n])
//   C = Ah*Bh + Ah*Bl + Al*Bh  (fp32 accumulate in registers)
// 128x128 CTA tile, K chunks of 64, 2-stage cp.async pipeline, 256 threads.
// Warp grid 2(m) x 4(n): each warp owns 64x32.
// ---------------------------------------------------------------------------
#define TB_    16384                 // one 128x64 bf16 tile
#define STAGE_ (4 * TB_)             // Ah|Al|Bh|Bl tiles per stage (64 KB)

__global__ __launch_bounds__(256) void gemm_mma(
    const __nv_bfloat16* __restrict__ Ah, const __nv_bfloat16* __restrict__ Al,
    const __nv_bfloat16* __restrict__ Bh, const __nv_bfloat16* __restrict__ Bl,
    const float* __restrict__ bias, float* __restrict__ C,
    int M, int N, int K)
{
    extern __shared__ char smem[];
    uint32_t sb = smem_u32(smem);
    int tid = threadIdx.x;
    int w = tid >> 5, lane = tid & 31;
    int bm = blockIdx.y * 128, bn = blockIdx.x * 128;
    int wm = w >> 2;       // 0..1  (64 rows each)
    int wn = w & 3;        // 0..3  (32 cols each)

    const __nv_bfloat16* gsrc[4] = {
        Ah + (size_t)bm * K, Al + (size_t)bm * K,
        Bh + (size_t)bn * K, Bl + (size_t)bn * K };

    // per-thread cp.async coordinates (4 reps x 16B per matrix)
    int lrow[4], lseg[4];
#pragma unroll
    for (int rep = 0; rep < 4; rep++) {
        int idx = rep * 256 + tid;
        lrow[rep] = idx >> 3;
        lseg[rep] = idx & 7;
    }

    float acc[4][4][4];
#pragma unroll
    for (int a = 0; a < 4; a++)
#pragma unroll
        for (int b = 0; b < 4; b++)
#pragma unroll
            for (int c = 0; c < 4; c++) acc[a][b][c] = 0.f;

    int nchunk = K >> 6;

    // prologue: stage 0 load
#pragma unroll
    for (int m = 0; m < 4; m++) {
        const __nv_bfloat16* g = gsrc[m];
        uint32_t tb = sb + m * TB_;
#pragma unroll
        for (int rep = 0; rep < 4; rep++)
            CP_ASYNC16(tb + SW128(lrow[rep] * 128 + lseg[rep] * 16),
                       g + (size_t)lrow[rep] * K + lseg[rep] * 8);
    }
    CP_COMMIT();

    for (int c = 0; c < nchunk; c++) {
        uint32_t stage = (c & 1) * STAGE_;
        if (c + 1 < nchunk) {
            int koff = (c + 1) << 6;
            uint32_t nstage = ((c + 1) & 1) * STAGE_;
#pragma unroll
            for (int m = 0; m < 4; m++) {
                const __nv_bfloat16* g = gsrc[m] + koff;
                uint32_t tb = sb + nstage + m * TB_;
#pragma unroll
                for (int rep = 0; rep < 4; rep++)
                    CP_ASYNC16(tb + SW128(lrow[rep] * 128 + lseg[rep] * 16),
                               g + (size_t)lrow[rep] * K + lseg[rep] * 8);
            }
            CP_COMMIT();
            CP_WAIT1();
        } else {
            CP_WAIT0();
        }
        __syncthreads();

        uint32_t bAh = sb + stage;
        uint32_t bAl = bAh + TB_;
        uint32_t bBh = bAl + TB_;
        uint32_t bBl = bBh + TB_;
        int rl = lane & 15, hf = lane >> 4;

#pragma unroll
        for (int k16 = 0; k16 < 4; k16++) {
            int kb = k16 * 32 + hf * 16;
            uint32_t ah[4][4], al[4][4], bh[2][4], bl[2][4];
#pragma unroll
            for (int mt = 0; mt < 4; mt++) {
                uint32_t sw = SW128((wm * 64 + mt * 16 + rl) * 128 + kb);
                LDSM4(ah[mt], bAh + sw);
                LDSM4(al[mt], bAl + sw);
            }
#pragma unroll
            for (int nt = 0; nt < 2; nt++) {
                uint32_t sw = SW128((wn * 32 + nt * 16 + rl) * 128 + kb);
                LDSM4(bh[nt], bBh + sw);
                LDSM4(bl[nt], bBl + sw);
            }
#pragma unroll
            for (int mt = 0; mt < 4; mt++)
#pragma unroll
                for (int n8 = 0; n8 < 4; n8++) {
                    int nt = n8 >> 1, sl = n8 & 1;
                    MMA16816(acc[mt][n8], ah[mt], bh[nt][sl], bh[nt][sl + 2]);
                    MMA16816(acc[mt][n8], al[mt], bh[nt][sl], bh[nt][sl + 2]);
                    MMA16816(acc[mt][n8], ah[mt], bl[nt][sl], bl[nt][sl + 2]);
                }
        }
        __syncthreads();
    }

    // Epilogue: register fragments -> gmem (float2, quad-contiguous 32B)
    int r4 = lane >> 2, c2 = (lane & 3) * 2;
#pragma unroll
    for (int mt = 0; mt < 4; mt++)
#pragma unroll
        for (int n8 = 0; n8 < 4; n8++) {
            int row = bm + wm * 64 + mt * 16 + r4;
            int col = bn + wn * 32 + n8 * 8 + c2;
            float b0 = 0.f, b1 = 0.f;
            if (bias) { b0 = bias[col]; b1 = bias[col + 1]; }
            float2 v0 = { acc[mt][n8][0] + b0, acc[mt][n8][1] + b1 };
            float2 v1 = { acc[mt][n8][2] + b0, acc[mt][n8][3] + b1 };
            *(float2*)(C + (size_t)row * N + col)       = v0;
            *(float2*)(C + (size_t)(row + 8) * N + col) = v1;
        }
}

// ---------------------------------------------------------------------------
// Fused causal attention with relative position (Music-Transformer skew).
// (unchanged from round-2 passing version)
// ---------------------------------------------------------------------------
__global__ __launch_bounds__(256, 2) void attn_fused(const float* __restrict__ Er)
{
    extern __shared__ float sm[];
    float* Qs = sm;
    float* Ks = Qs + 64 * SP_;
    float* Vs = Ks + 64 * SP_;
    float* Es = Vs + 64 * SP_;

    int tid = threadIdx.x;
    int n0 = blockIdx.x * 64;
    int bh = blockIdx.y;
    int b = bh >> 4, h = bh & 15;

    int ty = tid >> 4, tx = tid & 15;
    int r0 = ty * 4, c0 = tx * 4;

    const float* baseq = g_qkv + (size_t)b * N_ * (3 * DIM_) + h * HD_;

#pragma unroll
    for (int p = 0; p < 4; p++) {
        int row = p * 16 + ty;
        float4 v = *(const float4*)(baseq + (size_t)(n0 + row) * (3 * DIM_) + tx * 4);
        float* d = &Qs[row * SP_ + tx * 4];
        d[0] = v.x; d[1] = v.y; d[2] = v.z; d[3] = v.w;
    }

    float Mx[4], Lx[4], O[4][4];
#pragma unroll
    for (int i = 0; i < 4; i++) {
        Mx[i] = -3.0e38f; Lx[i] = 0.f;
        O[i][0] = O[i][1] = O[i][2] = O[i][3] = 0.f;
    }

    const float scale = 0.125f;

    for (int m0 = 0; m0 <= n0; m0 += 64) {
        __syncthreads();

#pragma unroll
        for (int p = 0; p < 4; p++) {
            int row = p * 16 + ty;
            const float* ksrc = baseq + DIM_ + (size_t)(m0 + row) * (3 * DIM_) + tx * 4;
            float4 kv = *(const float4*)(ksrc);
            float4 vv = *(const float4*)(ksrc + DIM_);
            float* kd = &Ks[row * SP_ + tx * 4];
            kd[0] = kv.x; kd[1] = kv.y; kd[2] = kv.z; kd[3] = kv.w;
            float* vd = &Vs[row * SP_ + tx * 4];
            vd[0] = vv.x; vd[1] = vv.y; vd[2] = vv.z; vd[3] = vv.w;
        }
        int ebase = N_ - 64 - n0 + m0;
#pragma unroll
        for (int p = 0; p < 8; p++) {
            int u = p * 16 + ty;
            if (u < 127) {
                int er = ebase + u;
                if (er > N_ - 1) er = N_ - 1;
                float4 ev = *(const float4*)(Er + (size_t)er * HD_ + tx * 4);
                float* ed = &Es[u * SP_ + tx * 4];
                ed[0] = ev.x; ed[1] = ev.y; ed[2] = ev.z; ed[3] = ev.w;
            }
        }
        __syncthreads();

        float S[4][4];
#pragma unroll
        for (int i = 0; i < 4; i++)
#pragma unroll
            for (int j = 0; j < 4; j++) S[i][j] = 0.f;

        int eo = c0 - r0 + 60;
#pragma unroll 8
        for (int d = 0; d < 64; d++) {
            float a0 = Qs[(r0 + 0) * SP_ + d];
            float a1 = Qs[(r0 + 1) * SP_ + d];
            float a2 = Qs[(r0 + 2) * SP_ + d];
            float a3 = Qs[(r0 + 3) * SP_ + d];
            float k0 = Ks[(c0 + 0) * SP_ + d];
            float k1 = Ks[(c0 + 1) * SP_ + d];
            float k2 = Ks[(c0 + 2) * SP_ + d];
            float k3 = Ks[(c0 + 3) * SP_ + d];
            float e[7];
#pragma unroll
            for (int t = 0; t < 7; t++) e[t] = Es[(eo + t) * SP_ + d];

            S[0][0] = fmaf(a0, k0 + e[3], S[0][0]);
            S[0][1] = fmaf(a0, k1 + e[4], S[0][1]);
            S[0][2] = fmaf(a0, k2 + e[5], S[0][2]);
            S[0][3] = fmaf(a0, k3 + e[6], S[0][3]);
            S[1][0] = fmaf(a1, k0 + e[2], S[1][0]);
            S[1][1] = fmaf(a1, k1 + e[3], S[1][1]);
            S[1][2] = fmaf(a1, k2 + e[4], S[1][2]);
            S[1][3] = fmaf(a1, k3 + e[5], S[1][3]);
            S[2][0] = fmaf(a2, k0 + e[1], S[2][0]);
            S[2][1] = fmaf(a2, k1 + e[2], S[2][1]);
            S[2][2] = fmaf(a2, k2 + e[3], S[2][2]);
            S[2][3] = fmaf(a2, k3 + e[4], S[2][3]);
            S[3][0] = fmaf(a3, k0 + e[0], S[3][0]);
            S[3][1] = fmaf(a3, k1 + e[1], S[3][1]);
            S[3][2] = fmaf(a3, k2 + e[2], S[3][2]);
            S[3][3] = fmaf(a3, k3 + e[3], S[3][3]);
        }

        bool diag = (m0 == n0);
#pragma unroll
        for (int i = 0; i < 4; i++)
#pragma unroll
            for (int j = 0; j < 4; j++) {
                float s = S[i][j] * scale;
                if (diag && (c0 + j > r0 + i)) s = -1.0e30f;
                S[i][j] = s;
            }

#pragma unroll
        for (int i = 0; i < 4; i++) {
            float rm = fmaxf(fmaxf(S[i][0], S[i][1]), fmaxf(S[i][2], S[i][3]));
            rm = fmaxf(rm, __shfl_xor_sync(0xffffffffu, rm, 1, 16));
            rm = fmaxf(rm, __shfl_xor_sync(0xffffffffu, rm, 2, 16));
            rm = fmaxf(rm, __shfl_xor_sync(0xffffffffu, rm, 4, 16));
            rm = fmaxf(rm, __shfl_xor_sync(0xffffffffu, rm, 8, 16));
            float mn = fmaxf(Mx[i], rm);
            float al = __expf(Mx[i] - mn);
            float rs = 0.f;
#pragma unroll
            for (int j = 0; j < 4; j++) {
                float pv = __expf(S[i][j] - mn);
                S[i][j] = pv;
                rs += pv;
            }
            rs += __shfl_xor_sync(0xffffffffu, rs, 1, 16);
            rs += __shfl_xor_sync(0xffffffffu, rs, 2, 16);
            rs += __shfl_xor_sync(0xffffffffu, rs, 4, 16);
            rs += __shfl_xor_sync(0xffffffffu, rs, 8, 16);
            Lx[i] = Lx[i] * al + rs;
            Mx[i] = mn;
            O[i][0] *= al; O[i][1] *= al; O[i][2] *= al; O[i][3] *= al;
        }

        __syncthreads();
        float* Ps = Es;
#pragma unroll
        for (int i = 0; i < 4; i++)
#pragma unroll
            for (int j = 0; j < 4; j++)
                Ps[(r0 + i) * SP_ + c0 + j] = S[i][j];
        __syncthreads();

#pragma unroll 8
        for (int c = 0; c < 64; c++) {
            float p0 = Ps[(r0 + 0) * SP_ + c];
            float p1 = Ps[(r0 + 1) * SP_ + c];
            float p2 = Ps[(r0 + 2) * SP_ + c];
            float p3 = Ps[(r0 + 3) * SP_ + c];
            float v0 = Vs[c * SP_ + c0 + 0];
            float v1 = Vs[c * SP_ + c0 + 1];
            float v2 = Vs[c * SP_ + c0 + 2];
            float v3 = Vs[c * SP_ + c0 + 3];
            O[0][0] = fmaf(p0, v0, O[0][0]); O[0][1] = fmaf(p0, v1, O[0][1]);
            O[0][2] = fmaf(p0, v2, O[0][2]); O[0][3] = fmaf(p0, v3, O[0][3]);
            O[1][0] = fmaf(p1, v0, O[1][0]); O[1][1] = fmaf(p1, v1, O[1][1]);
            O[1][2] = fmaf(p1, v2, O[1][2]); O[1][3] = fmaf(p1, v3, O[1][3]);
            O[2][0] = fmaf(p2, v0, O[2][0]); O[2][1] = fmaf(p2, v1, O[2][1]);
            O[2][2] = fmaf(p2, v2, O[2][2]); O[2][3] = fmaf(p2, v3, O[2][3]);
            O[3][0] = fmaf(p3, v0, O[3][0]); O[3][1] = fmaf(p3, v1, O[3][1]);
            O[3][2] = fmaf(p3, v2, O[3][2]); O[3][3] = fmaf(p3, v3, O[3][3]);
        }
    }

    float* op = g_attn + ((size_t)b * N_ + n0) * DIM_ + h * HD_;
#pragma unroll
    for (int i = 0; i < 4; i++) {
        float inv = 1.0f / Lx[i];
        float4 v;
        v.x = O[i][0] * inv; v.y = O[i][1] * inv;
        v.z = O[i][2] * inv; v.w = O[i][3] * inv;
        *(float4*)(op + (size_t)(r0 + i) * DIM_ + c0) = v;
    }
}

// ---------------------------------------------------------------------------
extern "C" void kernel_launch(void* const* d_in, const int* in_sizes, int n_in,
                              void* d_out, int out_size)
{
    const float* x      = (const float*)d_in[0];
    const float* W_qkv  = (const float*)d_in[1];
    const float* W_proj = (const float*)d_in[2];
    const float* b_proj = (const float*)d_in[3];
    const float* Er     = (const float*)d_in[4];
    float* out = (float*)d_out;

    float *qkv, *attn;
    __nv_bfloat16 *ah, *al, *wh, *wl, *ph, *pl;
    cudaGetSymbolAddress((void**)&qkv, g_qkv);
    cudaGetSymbolAddress((void**)&attn, g_attn);
    cudaGetSymbolAddress((void**)&ah, g_ah);
    cudaGetSymbolAddress((void**)&al, g_al);
    cudaGetSymbolAddress((void**)&wh, g_wh);
    cudaGetSymbolAddress((void**)&wl, g_wl);
    cudaGetSymbolAddress((void**)&ph, g_ph);
    cudaGetSymbolAddress((void**)&pl, g_pl);

    int attn_smem = (64 * 3 + 127) * SP_ * (int)sizeof(float);
    cudaFuncSetAttribute(attn_fused, cudaFuncAttributeMaxDynamicSharedMemorySize, attn_smem);
    int gemm_smem = 2 * STAGE_;   // 128 KB (2-stage pipeline)
    cudaFuncSetAttribute(gemm_mma, cudaFuncAttributeMaxDynamicSharedMemorySize, gemm_smem);

    int n_x  = ROWS_ * DIM_;              // 4M
    int n_wq = 3 * DIM_ * DIM_;           // 3M
    int n_wp = DIM_ * DIM_;               // 1M

    // Split conversions (inputs)
    split_bf16<<<n_x  / 1024, 256>>>(x,      ah, al, n_x);
    split_bf16<<<n_wq / 1024, 256>>>(W_qkv,  wh, wl, n_wq);
    split_bf16<<<n_wp / 1024, 256>>>(W_proj, ph, pl, n_wp);

    // 1) QKV projection: [4096,1024] @ [3072,1024]^T -> g_qkv
    gemm_mma<<<dim3(3 * DIM_ / 128, ROWS_ / 128), 256, gemm_smem>>>(
        ah, al, wh, wl, nullptr, qkv, ROWS_, 3 * DIM_, DIM_);

    // 2) Fused causal relative attention -> g_attn
    attn_fused<<<dim3(N_ / 64, B_ * H_), 256, attn_smem>>>(Er);

    // Split conversion of attention output (reuse x buffers)
    split_bf16<<<n_x / 1024, 256>>>(attn, ah, al, n_x);

    // 3) Output projection + bias -> out
    gemm_mma<<<dim3(DIM_ / 128, ROWS_ / 128), 256, gemm_smem>>>(
        ah, al, ph, pl, b_proj, out, ROWS_, DIM_, DIM_);
}

// round 9
// speedup vs baseline: 2.4860x; 1.5139x over previous
#include <cuda_runtime.h>
#include <cuda_bf16.h>
#include <math.h>
#include <stdint.h>

#define B_    4
#define N_    1024
#define DIM_  1024
#define H_    16
#define HD_   64
#define ROWS_ (B_ * N_)          // 4096

// ---------------------------------------------------------------------------
// Scratch (device globals: allocation-free rule)
// ---------------------------------------------------------------------------
__device__ float g_qkv[(size_t)ROWS_ * 3 * DIM_];   // [4096][3072]
__device__ float g_attn[(size_t)ROWS_ * DIM_];      // [4096][1024]
__device__ __nv_bfloat16 g_ah[(size_t)ROWS_ * DIM_];       // x / attn hi
__device__ __nv_bfloat16 g_al[(size_t)ROWS_ * DIM_];       // x / attn lo
__device__ __nv_bfloat16 g_wh[(size_t)3 * DIM_ * DIM_];    // W_qkv hi
__device__ __nv_bfloat16 g_wl[(size_t)3 * DIM_ * DIM_];    // W_qkv lo
__device__ __nv_bfloat16 g_ph[(size_t)DIM_ * DIM_];        // W_proj hi
__device__ __nv_bfloat16 g_pl[(size_t)DIM_ * DIM_];        // W_proj lo
// head-contiguous split buffers for attention  [bh][n][d] / [bh][d][n]
__device__ __nv_bfloat16 g_qh[(size_t)64 * 1024 * 64];
__device__ __nv_bfloat16 g_ql[(size_t)64 * 1024 * 64];
__device__ __nv_bfloat16 g_kh[(size_t)64 * 1024 * 64];
__device__ __nv_bfloat16 g_kl[(size_t)64 * 1024 * 64];
__device__ __nv_bfloat16 g_vth[(size_t)64 * 64 * 1024];    // V^T
__device__ __nv_bfloat16 g_vtl[(size_t)64 * 64 * 1024];
__device__ __nv_bfloat16 g_erh[(size_t)1024 * 64];
__device__ __nv_bfloat16 g_erl[(size_t)1024 * 64];

// ---------------------------------------------------------------------------
// Portable PTX helpers (sm_80+ family-generic)
// ---------------------------------------------------------------------------
__device__ __forceinline__ uint32_t smem_u32(const void* p) {
    uint32_t a;
    asm("{ .reg .u64 t; cvta.to.shared.u64 t, %1; cvt.u32.u64 %0, t; }"
        : "=r"(a) : "l"(p));
    return a;
}

#define CP_ASYNC16(saddr, gptr) \
    asm volatile("cp.async.cg.shared.global [%0], [%1], 16;" \
        :: "r"(saddr), "l"(gptr) : "memory")
#define CP_COMMIT() asm volatile("cp.async.commit_group;" ::: "memory")
#define CP_WAIT1()  asm volatile("cp.async.wait_group 1;" ::: "memory")
#define CP_WAIT0()  asm volatile("cp.async.wait_group 0;" ::: "memory")

#define LDSM4(r, addr) \
    asm volatile("ldmatrix.sync.aligned.m8n8.x4.shared.b16 {%0,%1,%2,%3}, [%4];" \
        : "=r"((r)[0]), "=r"((r)[1]), "=r"((r)[2]), "=r"((r)[3]) : "r"(addr))

#define MMA16816(d, a, b0, b1) \
    asm volatile("mma.sync.aligned.m16n8k16.row.col.f32.bf16.bf16.f32 " \
        "{%0,%1,%2,%3}, {%4,%5,%6,%7}, {%8,%9}, {%0,%1,%2,%3};" \
        : "+f"((d)[0]), "+f"((d)[1]), "+f"((d)[2]), "+f"((d)[3]) \
        : "r"((a)[0]), "r"((a)[1]), "r"((a)[2]), "r"((a)[3]), \
          "r"(b0), "r"(b1))

#define SW128(off) ((off) ^ (((off) >> 3) & 0x70))

__device__ __forceinline__ void split2(float a, float b, uint32_t& h, uint32_t& l) {
    __nv_bfloat16 ha = __float2bfloat16(a), hb = __float2bfloat16(b);
    __nv_bfloat16 la = __float2bfloat16(a - __bfloat162float(ha));
    __nv_bfloat16 lb = __float2bfloat16(b - __bfloat162float(hb));
    __nv_bfloat162 th(ha, hb), tl(la, lb);
    h = *(uint32_t*)&th; l = *(uint32_t*)&tl;
}

// ---------------------------------------------------------------------------
// fp32 -> (bf16 hi, bf16 lo) split conversion
// ---------------------------------------------------------------------------
__global__ __launch_bounds__(256) void split_bf16(
    const float* __restrict__ in, __nv_bfloat16* __restrict__ hi,
    __nv_bfloat16* __restrict__ lo, int n)
{
    int i = (blockIdx.x * 256 + threadIdx.x) * 4;
    if (i >= n) return;
    float4 v = *(const float4*)(in + i);
    uint32_t h01, l01, h23, l23;
    split2(v.x, v.y, h01, l01); split2(v.z, v.w, h23, l23);
    *(uint32_t*)(hi + i) = h01; *(uint32_t*)(hi + i + 2) = h23;
    *(uint32_t*)(lo + i) = l01; *(uint32_t*)(lo + i + 2) = l23;
}

// ---------------------------------------------------------------------------
// bf16-split GEMM on mma.sync (unchanged, verified round-7)
// ---------------------------------------------------------------------------
#define TB_    16384
#define STAGE_ (4 * TB_)

__global__ __launch_bounds__(256) void gemm_mma(
    const __nv_bfloat16* __restrict__ Ah, const __nv_bfloat16* __restrict__ Al,
    const __nv_bfloat16* __restrict__ Bh, const __nv_bfloat16* __restrict__ Bl,
    const float* __restrict__ bias, float* __restrict__ C,
    int M, int N, int K)
{
    extern __shared__ char smem[];
    uint32_t sb = smem_u32(smem);
    int tid = threadIdx.x;
    int w = tid >> 5, lane = tid & 31;
    int bm = blockIdx.y * 128, bn = blockIdx.x * 128;
    int wm = w >> 2, wn = w & 3;

    const __nv_bfloat16* gsrc[4] = {
        Ah + (size_t)bm * K, Al + (size_t)bm * K,
        Bh + (size_t)bn * K, Bl + (size_t)bn * K };

    int lrow[4], lseg[4];
#pragma unroll
    for (int rep = 0; rep < 4; rep++) {
        int idx = rep * 256 + tid;
        lrow[rep] = idx >> 3;
        lseg[rep] = idx & 7;
    }

    float acc[4][4][4];
#pragma unroll
    for (int a = 0; a < 4; a++)
#pragma unroll
        for (int b = 0; b < 4; b++)
#pragma unroll
            for (int c = 0; c < 4; c++) acc[a][b][c] = 0.f;

    int nchunk = K >> 6;

#pragma unroll
    for (int m = 0; m < 4; m++) {
        const __nv_bfloat16* g = gsrc[m];
        uint32_t tb = sb + m * TB_;
#pragma unroll
        for (int rep = 0; rep < 4; rep++)
            CP_ASYNC16(tb + SW128(lrow[rep] * 128 + lseg[rep] * 16),
                       g + (size_t)lrow[rep] * K + lseg[rep] * 8);
    }
    CP_COMMIT();

    for (int c = 0; c < nchunk; c++) {
        uint32_t stage = (c & 1) * STAGE_;
        if (c + 1 < nchunk) {
            int koff = (c + 1) << 6;
            uint32_t nstage = ((c + 1) & 1) * STAGE_;
#pragma unroll
            for (int m = 0; m < 4; m++) {
                const __nv_bfloat16* g = gsrc[m] + koff;
                uint32_t tb = sb + nstage + m * TB_;
#pragma unroll
                for (int rep = 0; rep < 4; rep++)
                    CP_ASYNC16(tb + SW128(lrow[rep] * 128 + lseg[rep] * 16),
                               g + (size_t)lrow[rep] * K + lseg[rep] * 8);
            }
            CP_COMMIT();
            CP_WAIT1();
        } else {
            CP_WAIT0();
        }
        __syncthreads();

        uint32_t bAh = sb + stage;
        uint32_t bAl = bAh + TB_;
        uint32_t bBh = bAl + TB_;
        uint32_t bBl = bBh + TB_;
        int rl = lane & 15, hf = lane >> 4;

#pragma unroll
        for (int k16 = 0; k16 < 4; k16++) {
            int kb = k16 * 32 + hf * 16;
            uint32_t ah[4][4], al[4][4], bh[2][4], bl[2][4];
#pragma unroll
            for (int mt = 0; mt < 4; mt++) {
                uint32_t sw = SW128((wm * 64 + mt * 16 + rl) * 128 + kb);
                LDSM4(ah[mt], bAh + sw);
                LDSM4(al[mt], bAl + sw);
            }
#pragma unroll
            for (int nt = 0; nt < 2; nt++) {
                uint32_t sw = SW128((wn * 32 + nt * 16 + rl) * 128 + kb);
                LDSM4(bh[nt], bBh + sw);
                LDSM4(bl[nt], bBl + sw);
            }
#pragma unroll
            for (int mt = 0; mt < 4; mt++)
#pragma unroll
                for (int n8 = 0; n8 < 4; n8++) {
                    int nt = n8 >> 1, sl = n8 & 1;
                    MMA16816(acc[mt][n8], ah[mt], bh[nt][sl], bh[nt][sl + 2]);
                    MMA16816(acc[mt][n8], al[mt], bh[nt][sl], bh[nt][sl + 2]);
                    MMA16816(acc[mt][n8], ah[mt], bl[nt][sl], bl[nt][sl + 2]);
                }
        }
        __syncthreads();
    }

    int r4 = lane >> 2, c2 = (lane & 3) * 2;
#pragma unroll
    for (int mt = 0; mt < 4; mt++)
#pragma unroll
        for (int n8 = 0; n8 < 4; n8++) {
            int row = bm + wm * 64 + mt * 16 + r4;
            int col = bn + wn * 32 + n8 * 8 + c2;
            float b0 = 0.f, b1 = 0.f;
            if (bias) { b0 = bias[col]; b1 = bias[col + 1]; }
            float2 v0 = { acc[mt][n8][0] + b0, acc[mt][n8][1] + b1 };
            float2 v1 = { acc[mt][n8][2] + b0, acc[mt][n8][3] + b1 };
            *(float2*)(C + (size_t)row * N + col)       = v0;
            *(float2*)(C + (size_t)(row + 8) * N + col) = v1;
        }
}

// ---------------------------------------------------------------------------
// split_heads: g_qkv fp32 -> head-contiguous bf16 hi/lo Q, K, V^T
// grid (16 ntiles, 64 bh), 256 threads
// ---------------------------------------------------------------------------
__global__ __launch_bounds__(256) void split_heads()
{
    __shared__ float vs[64][65];
    int tid = threadIdx.x;
    int n0 = blockIdx.x * 64, bh = blockIdx.y;
    int b = bh >> 4, h = bh & 15;
    const float* src = g_qkv + ((size_t)(b * 1024) + n0) * 3072 + h * 64;
    size_t obase = ((size_t)bh * 1024 + n0) * 64;

#pragma unroll
    for (int sel = 0; sel < 2; sel++) {
        __nv_bfloat16* dh = (sel ? g_kh : g_qh) + obase;
        __nv_bfloat16* dl = (sel ? g_kl : g_ql) + obase;
#pragma unroll
        for (int rep = 0; rep < 4; rep++) {
            int i = rep * 256 + tid, row = i >> 4, d4 = (i & 15) * 4;
            float4 v = *(const float4*)(src + (size_t)row * 3072 + sel * 1024 + d4);
            uint32_t h01, l01, h23, l23;
            split2(v.x, v.y, h01, l01); split2(v.z, v.w, h23, l23);
            *(uint32_t*)(dh + row * 64 + d4)     = h01;
            *(uint32_t*)(dh + row * 64 + d4 + 2) = h23;
            *(uint32_t*)(dl + row * 64 + d4)     = l01;
            *(uint32_t*)(dl + row * 64 + d4 + 2) = l23;
        }
    }
    // V tile -> smem -> transposed split
#pragma unroll
    for (int rep = 0; rep < 4; rep++) {
        int i = rep * 256 + tid, row = i >> 4, d4 = (i & 15) * 4;
        float4 v = *(const float4*)(src + (size_t)row * 3072 + 2048 + d4);
        vs[row][d4] = v.x; vs[row][d4 + 1] = v.y;
        vs[row][d4 + 2] = v.z; vs[row][d4 + 3] = v.w;
    }
    __syncthreads();
#pragma unroll
    for (int rep = 0; rep < 4; rep++) {
        int i = rep * 256 + tid, d = i >> 4, m4 = (i & 15) * 4;
        float x0 = vs[m4][d], x1 = vs[m4 + 1][d], x2 = vs[m4 + 2][d], x3 = vs[m4 + 3][d];
        uint32_t h01, l01, h23, l23;
        split2(x0, x1, h01, l01); split2(x2, x3, h23, l23);
        __nv_bfloat16* dh = g_vth + ((size_t)bh * 64 + d) * 1024 + n0 + m4;
        __nv_bfloat16* dl = g_vtl + ((size_t)bh * 64 + d) * 1024 + n0 + m4;
        *(uint32_t*)dh = h01; *(uint32_t*)(dh + 2) = h23;
        *(uint32_t*)dl = l01; *(uint32_t*)(dl + 2) = l23;
    }
}

// ---------------------------------------------------------------------------
// attn_mma: causal relative flash-attention on mma.sync (bf16 split)
// block = (qtile n0, bh); 256 threads = 8 warps: wm = w&3 (16-row band),
// wn = w>>2 (col half). SMEM (bytes):
//   Qh 0 / Ql 8K | stages@16K (64K each: Kh,Kl,Vth,Vtl,Eh(16K),El(16K))
//   R fp32 [64][132] @147456 | Ph @181248 / Pl @189440 | redA @197632 / redB @198144
// ---------------------------------------------------------------------------
#define ASMEM_ 198656

__global__ __launch_bounds__(256, 1) void attn_mma()
{
    extern __shared__ char smem[];
    uint32_t sb = smem_u32(smem);
    const int tid = threadIdx.x, w = tid >> 5, lane = tid & 31;
    const int wm = w & 3, wn = w >> 2;
    const int n0 = blockIdx.x * 64, bh = blockIdx.y;
    const int rl = lane & 15, hf = lane >> 4;
    const int r4 = lane >> 2, c2 = (lane & 3) * 2;

    const uint32_t sQh = sb, sQl = sb + 8192;
    float* Rsm  = (float*)(smem + 147456);          // pitch 132 floats
    float* redA = (float*)(smem + 197632);          // [64][2] row max
    float* redB = (float*)(smem + 198144);          // [64][2] row sum

    // ---- Q tile load (once)
    {
        const __nv_bfloat16* qh = g_qh + ((size_t)bh * 1024 + n0) * 64;
        const __nv_bfloat16* ql = g_ql + ((size_t)bh * 1024 + n0) * 64;
#pragma unroll
        for (int rep = 0; rep < 2; rep++) {
            int i = rep * 256 + tid, row = i >> 3, seg = i & 7;
            uint32_t sw = SW128(row * 128 + seg * 16);
            CP_ASYNC16(sQh + sw, qh + (size_t)row * 64 + seg * 8);
            CP_ASYNC16(sQl + sw, ql + (size_t)row * 64 + seg * 8);
        }
    }

    // ---- stage loader (K,V^T,E band for key tile m0)
    auto load_stage = [&](int s, int m0) {
        uint32_t st = sb + 16384 + s * 65536;
        const __nv_bfloat16* kh = g_kh + ((size_t)bh * 1024 + m0) * 64;
        const __nv_bfloat16* kl = g_kl + ((size_t)bh * 1024 + m0) * 64;
#pragma unroll
        for (int rep = 0; rep < 2; rep++) {
            int i = rep * 256 + tid, row = i >> 3, seg = i & 7;
            uint32_t sw = SW128(row * 128 + seg * 16);
            CP_ASYNC16(st + sw,        kh + (size_t)row * 64 + seg * 8);
            CP_ASYNC16(st + 8192 + sw, kl + (size_t)row * 64 + seg * 8);
        }
#pragma unroll
        for (int rep = 0; rep < 2; rep++) {
            int i = rep * 256 + tid, row = i >> 3, seg = i & 7;
            uint32_t sw = SW128(row * 128 + seg * 16);
            CP_ASYNC16(st + 16384 + sw,
                       g_vth + ((size_t)bh * 64 + row) * 1024 + m0 + seg * 8);
            CP_ASYNC16(st + 24576 + sw,
                       g_vtl + ((size_t)bh * 64 + row) * 1024 + m0 + seg * 8);
        }
        int ebase = 960 - n0 + m0;
#pragma unroll
        for (int rep = 0; rep < 4; rep++) {
            int i = rep * 256 + tid, row = i >> 3, seg = i & 7;
            int er = ebase + row; if (er > 1023) er = 1023;
            uint32_t sw = SW128(row * 128 + seg * 16);
            CP_ASYNC16(st + 32768 + sw, g_erh + (size_t)er * 64 + seg * 8);
            CP_ASYNC16(st + 49152 + sw, g_erl + (size_t)er * 64 + seg * 8);
        }
    };

    float O[4][4];
#pragma unroll
    for (int a = 0; a < 4; a++)
#pragma unroll
        for (int c = 0; c < 4; c++) O[a][c] = 0.f;
    float Mx[2] = { -3.0e38f, -3.0e38f }, Lx[2] = { 0.f, 0.f };

    load_stage(0, 0);
    CP_COMMIT();

    const int nit = (n0 >> 6) + 1;
    for (int it = 0; it < nit; it++) {
        if (it + 1 < nit) { load_stage((it + 1) & 1, (it + 1) * 64); CP_COMMIT(); CP_WAIT1(); }
        else              { CP_WAIT0(); }
        __syncthreads();

        uint32_t st = sb + 16384 + (it & 1) * 65536;

        // ---- content (Sc 64x64) + rel (Sr 64x128) MMAs
        float Sc[4][4], Sr[8][4];
#pragma unroll
        for (int a = 0; a < 4; a++)
#pragma unroll
            for (int c = 0; c < 4; c++) Sc[a][c] = 0.f;
#pragma unroll
        for (int a = 0; a < 8; a++)
#pragma unroll
            for (int c = 0; c < 4; c++) Sr[a][c] = 0.f;

#pragma unroll
        for (int k16 = 0; k16 < 4; k16++) {
            int kb = k16 * 32 + hf * 16;
            uint32_t aqh[4], aql[4];
            uint32_t swA = SW128((wm * 16 + rl) * 128 + kb);
            LDSM4(aqh, sQh + swA);
            LDSM4(aql, sQl + swA);
            uint32_t bkh[2][4], bkl[2][4];
#pragma unroll
            for (int nt = 0; nt < 2; nt++) {
                uint32_t sw = SW128((wn * 32 + nt * 16 + rl) * 128 + kb);
                LDSM4(bkh[nt], st + sw);
                LDSM4(bkl[nt], st + 8192 + sw);
            }
#pragma unroll
            for (int n8 = 0; n8 < 4; n8++) {
                int nt = n8 >> 1, sl = n8 & 1;
                MMA16816(Sc[n8], aqh, bkh[nt][sl], bkh[nt][sl + 2]);
                MMA16816(Sc[n8], aql, bkh[nt][sl], bkh[nt][sl + 2]);
                MMA16816(Sc[n8], aqh, bkl[nt][sl], bkl[nt][sl + 2]);
            }
            uint32_t beh[4][4], bel[4][4];
#pragma unroll
            for (int nt = 0; nt < 4; nt++) {
                uint32_t sw = SW128((wn * 64 + nt * 16 + rl) * 128 + kb);
                LDSM4(beh[nt], st + 32768 + sw);
                LDSM4(bel[nt], st + 49152 + sw);
            }
#pragma unroll
            for (int n8 = 0; n8 < 8; n8++) {
                int nt = n8 >> 1, sl = n8 & 1;
                MMA16816(Sr[n8], aqh, beh[nt][sl], beh[nt][sl + 2]);
                MMA16816(Sr[n8], aql, beh[nt][sl], beh[nt][sl + 2]);
                MMA16816(Sr[n8], aqh, bel[nt][sl], bel[nt][sl + 2]);
            }
        }

        // ---- stage rel to SMEM (fp32 [64][132])
        {
            int i0 = wm * 16 + r4;
#pragma unroll
            for (int n8 = 0; n8 < 8; n8++) {
                int u = wn * 64 + n8 * 8 + c2;
                *(float2*)(Rsm + (size_t)i0 * 132 + u)       = make_float2(Sr[n8][0], Sr[n8][1]);
                *(float2*)(Rsm + (size_t)(i0 + 8) * 132 + u) = make_float2(Sr[n8][2], Sr[n8][3]);
            }
        }
        __syncthreads();

        // ---- gather rel diagonal band + scale + causal mask
        const bool diag = (it == nit - 1);
        int i0 = wm * 16 + r4, i1 = i0 + 8;
#pragma unroll
        for (int n8 = 0; n8 < 4; n8++) {
            int j = wn * 32 + n8 * 8 + c2;
            Sc[n8][0] = (Sc[n8][0] + Rsm[(size_t)i0 * 132 + (j     - i0 + 63)]) * 0.125f;
            Sc[n8][1] = (Sc[n8][1] + Rsm[(size_t)i0 * 132 + (j + 1 - i0 + 63)]) * 0.125f;
            Sc[n8][2] = (Sc[n8][2] + Rsm[(size_t)i1 * 132 + (j     - i1 + 63)]) * 0.125f;
            Sc[n8][3] = (Sc[n8][3] + Rsm[(size_t)i1 * 132 + (j + 1 - i1 + 63)]) * 0.125f;
            if (diag) {
                if (j     > i0) Sc[n8][0] = -1.0e30f;
                if (j + 1 > i0) Sc[n8][1] = -1.0e30f;
                if (j     > i1) Sc[n8][2] = -1.0e30f;
                if (j + 1 > i1) Sc[n8][3] = -1.0e30f;
            }
        }

        // ---- row max (quad shuffle + cross-warp SMEM exchange)
        float m0_ = -3.0e38f, m1_ = -3.0e38f;
#pragma unroll
        for (int n8 = 0; n8 < 4; n8++) {
            m0_ = fmaxf(m0_, fmaxf(Sc[n8][0], Sc[n8][1]));
            m1_ = fmaxf(m1_, fmaxf(Sc[n8][2], Sc[n8][3]));
        }
        m0_ = fmaxf(m0_, __shfl_xor_sync(0xffffffffu, m0_, 1));
        m0_ = fmaxf(m0_, __shfl_xor_sync(0xffffffffu, m0_, 2));
        m1_ = fmaxf(m1_, __shfl_xor_sync(0xffffffffu, m1_, 1));
        m1_ = fmaxf(m1_, __shfl_xor_sync(0xffffffffu, m1_, 2));
        if ((lane & 3) == 0) {
            redA[i0 * 2 + wn] = m0_;
            redA[i1 * 2 + wn] = m1_;
        }
        __syncthreads();
        m0_ = fmaxf(redA[i0 * 2], redA[i0 * 2 + 1]);
        m1_ = fmaxf(redA[i1 * 2], redA[i1 * 2 + 1]);

        float mn0 = fmaxf(Mx[0], m0_), mn1 = fmaxf(Mx[1], m1_);
        float al0 = __expf(Mx[0] - mn0), al1 = __expf(Mx[1] - mn1);

        // ---- exp + row sum
        float s0 = 0.f, s1 = 0.f;
#pragma unroll
        for (int n8 = 0; n8 < 4; n8++) {
            Sc[n8][0] = __expf(Sc[n8][0] - mn0);
            Sc[n8][1] = __expf(Sc[n8][1] - mn0);
            Sc[n8][2] = __expf(Sc[n8][2] - mn1);
            Sc[n8][3] = __expf(Sc[n8][3] - mn1);
            s0 += Sc[n8][0] + Sc[n8][1];
            s1 += Sc[n8][2] + Sc[n8][3];
        }
        s0 += __shfl_xor_sync(0xffffffffu, s0, 1);
        s0 += __shfl_xor_sync(0xffffffffu, s0, 2);
        s1 += __shfl_xor_sync(0xffffffffu, s1, 1);
        s1 += __shfl_xor_sync(0xffffffffu, s1, 2);
        if ((lane & 3) == 0) {
            redB[i0 * 2 + wn] = s0;
            redB[i1 * 2 + wn] = s1;
        }
        __syncthreads();
        s0 = redB[i0 * 2] + redB[i0 * 2 + 1];
        s1 = redB[i1 * 2] + redB[i1 * 2 + 1];

        Lx[0] = Lx[0] * al0 + s0; Mx[0] = mn0;
        Lx[1] = Lx[1] * al1 + s1; Mx[1] = mn1;
#pragma unroll
        for (int n8 = 0; n8 < 4; n8++) {
            O[n8][0] *= al0; O[n8][1] *= al0;
            O[n8][2] *= al1; O[n8][3] *= al1;
        }

        // ---- P -> SMEM (bf16 split, swizzled rows i x 64 cols)
#pragma unroll
        for (int n8 = 0; n8 < 4; n8++) {
            int jb = (wn * 32 + n8 * 8 + c2) * 2;   // byte col offset
            uint32_t h01, l01, h23, l23;
            split2(Sc[n8][0], Sc[n8][1], h01, l01);
            split2(Sc[n8][2], Sc[n8][3], h23, l23);
            uint32_t o0 = SW128(i0 * 128 + jb), o1 = SW128(i1 * 128 + jb);
            *(uint32_t*)(smem + 181248 + o0) = h01;
            *(uint32_t*)(smem + 189440 + o0) = l01;
            *(uint32_t*)(smem + 181248 + o1) = h23;
            *(uint32_t*)(smem + 189440 + o1) = l23;
        }
        __syncthreads();

        // ---- P @ V^T  (A = P rows, B = Vt rows d, k = keys)
#pragma unroll
        for (int k16 = 0; k16 < 4; k16++) {
            int kb = k16 * 32 + hf * 16;
            uint32_t aph[4], apl[4];
            uint32_t swA = SW128((wm * 16 + rl) * 128 + kb);
            LDSM4(aph, sb + 181248 + swA);
            LDSM4(apl, sb + 189440 + swA);
            uint32_t bvh[2][4], bvl[2][4];
#pragma unroll
            for (int nt = 0; nt < 2; nt++) {
                uint32_t sw = SW128((wn * 32 + nt * 16 + rl) * 128 + kb);
                LDSM4(bvh[nt], st + 16384 + sw);
                LDSM4(bvl[nt], st + 24576 + sw);
            }
#pragma unroll
            for (int n8 = 0; n8 < 4; n8++) {
                int nt = n8 >> 1, sl = n8 & 1;
                MMA16816(O[n8], aph, bvh[nt][sl], bvh[nt][sl + 2]);
                MMA16816(O[n8], apl, bvh[nt][sl], bvh[nt][sl + 2]);
                MMA16816(O[n8], aph, bvl[nt][sl], bvl[nt][sl + 2]);
            }
        }
        __syncthreads();   // protect stage/P/R reuse next iteration
    }

    // ---- normalize + write out: g_attn[b][n0+i][h*64 + d]
    {
        int b = bh >> 4, h = bh & 15;
        float inv0 = 1.0f / Lx[0], inv1 = 1.0f / Lx[1];
        float* op = g_attn + ((size_t)(b * 1024) + n0) * 1024 + h * 64;
        int i0 = wm * 16 + r4;
#pragma unroll
        for (int n8 = 0; n8 < 4; n8++) {
            int col = wn * 32 + n8 * 8 + c2;
            *(float2*)(op + (size_t)i0 * 1024 + col) =
                make_float2(O[n8][0] * inv0, O[n8][1] * inv0);
            *(float2*)(op + (size_t)(i0 + 8) * 1024 + col) =
                make_float2(O[n8][2] * inv1, O[n8][3] * inv1);
        }
    }
}

// ---------------------------------------------------------------------------
extern "C" void kernel_launch(void* const* d_in, const int* in_sizes, int n_in,
                              void* d_out, int out_size)
{
    const float* x      = (const float*)d_in[0];
    const float* W_qkv  = (const float*)d_in[1];
    const float* W_proj = (const float*)d_in[2];
    const float* b_proj = (const float*)d_in[3];
    const float* Er     = (const float*)d_in[4];
    float* out = (float*)d_out;

    float *qkv, *attn;
    __nv_bfloat16 *ah, *al, *wh, *wl, *ph, *pl, *erh, *erl;
    cudaGetSymbolAddress((void**)&qkv, g_qkv);
    cudaGetSymbolAddress((void**)&attn, g_attn);
    cudaGetSymbolAddress((void**)&ah, g_ah);
    cudaGetSymbolAddress((void**)&al, g_al);
    cudaGetSymbolAddress((void**)&wh, g_wh);
    cudaGetSymbolAddress((void**)&wl, g_wl);
    cudaGetSymbolAddress((void**)&ph, g_ph);
    cudaGetSymbolAddress((void**)&pl, g_pl);
    cudaGetSymbolAddress((void**)&erh, g_erh);
    cudaGetSymbolAddress((void**)&erl, g_erl);

    int gemm_smem = 2 * STAGE_;   // 128 KB
    cudaFuncSetAttribute(gemm_mma, cudaFuncAttributeMaxDynamicSharedMemorySize, gemm_smem);
    cudaFuncSetAttribute(attn_mma, cudaFuncAttributeMaxDynamicSharedMemorySize, ASMEM_);

    int n_x  = ROWS_ * DIM_;
    int n_wq = 3 * DIM_ * DIM_;
    int n_wp = DIM_ * DIM_;

    split_bf16<<<n_x  / 1024, 256>>>(x,      ah, al, n_x);
    split_bf16<<<n_wq / 1024, 256>>>(W_qkv,  wh, wl, n_wq);
    split_bf16<<<n_wp / 1024, 256>>>(W_proj, ph, pl, n_wp);
    split_bf16<<<64, 256>>>(Er, erh, erl, 1024 * 64);

    // 1) QKV projection
    gemm_mma<<<dim3(3 * DIM_ / 128, ROWS_ / 128), 256, gemm_smem>>>(
        ah, al, wh, wl, nullptr, qkv, ROWS_, 3 * DIM_, DIM_);

    // 2) head split + tensor-core attention
    split_heads<<<dim3(16, 64), 256>>>();
    attn_mma<<<dim3(16, 64), 256, ASMEM_>>>();

    // 3) output projection
    split_bf16<<<n_x / 1024, 256>>>(attn, ah, al, n_x);
    gemm_mma<<<dim3(DIM_ / 128, ROWS_ / 128), 256, gemm_smem>>>(
        ah, al, ph, pl, b_proj, out, ROWS_, DIM_, DIM_);
}

// round 11
// speedup vs baseline: 2.4963x; 1.0041x over previous
#include <cuda_runtime.h>
#include <cuda_bf16.h>
#include <math.h>
#include <stdint.h>

#define B_    4
#define N_    1024
#define DIM_  1024
#define H_    16
#define HD_   64
#define ROWS_ (B_ * N_)          // 4096

// ---------------------------------------------------------------------------
// Scratch (device globals: allocation-free rule)
// ---------------------------------------------------------------------------
__device__ float g_qkv[(size_t)ROWS_ * 3 * DIM_];   // [4096][3072]
__device__ float g_attn[(size_t)ROWS_ * DIM_];      // [4096][1024]
__device__ __nv_bfloat16 g_ah[(size_t)ROWS_ * DIM_];       // x / attn hi
__device__ __nv_bfloat16 g_al[(size_t)ROWS_ * DIM_];       // x / attn lo
__device__ __nv_bfloat16 g_wh[(size_t)3 * DIM_ * DIM_];    // W_qkv hi
__device__ __nv_bfloat16 g_wl[(size_t)3 * DIM_ * DIM_];    // W_qkv lo
__device__ __nv_bfloat16 g_ph[(size_t)DIM_ * DIM_];        // W_proj hi
__device__ __nv_bfloat16 g_pl[(size_t)DIM_ * DIM_];        // W_proj lo
// head-contiguous split buffers for attention  [bh][n][d] / [bh][d][n]
__device__ __nv_bfloat16 g_qh[(size_t)64 * 1024 * 64];
__device__ __nv_bfloat16 g_ql[(size_t)64 * 1024 * 64];
__device__ __nv_bfloat16 g_kh[(size_t)64 * 1024 * 64];
__device__ __nv_bfloat16 g_kl[(size_t)64 * 1024 * 64];
__device__ __nv_bfloat16 g_vth[(size_t)64 * 64 * 1024];    // V^T
__device__ __nv_bfloat16 g_vtl[(size_t)64 * 64 * 1024];
__device__ __nv_bfloat16 g_erh[(size_t)1024 * 64];
__device__ __nv_bfloat16 g_erl[(size_t)1024 * 64];

// ---------------------------------------------------------------------------
// Portable PTX helpers (sm_80+ family-generic)
// ---------------------------------------------------------------------------
__device__ __forceinline__ uint32_t smem_u32(const void* p) {
    uint32_t a;
    asm("{ .reg .u64 t; cvta.to.shared.u64 t, %1; cvt.u32.u64 %0, t; }"
        : "=r"(a) : "l"(p));
    return a;
}

#define CP_ASYNC16(saddr, gptr) \
    asm volatile("cp.async.cg.shared.global [%0], [%1], 16;" \
        :: "r"(saddr), "l"(gptr) : "memory")
#define CP_COMMIT() asm volatile("cp.async.commit_group;" ::: "memory")
#define CP_WAIT1()  asm volatile("cp.async.wait_group 1;" ::: "memory")
#define CP_WAIT0()  asm volatile("cp.async.wait_group 0;" ::: "memory")

#define LDSM4(r, addr) \
    asm volatile("ldmatrix.sync.aligned.m8n8.x4.shared.b16 {%0,%1,%2,%3}, [%4];" \
        : "=r"((r)[0]), "=r"((r)[1]), "=r"((r)[2]), "=r"((r)[3]) : "r"(addr))

#define MMA16816(d, a, b0, b1) \
    asm volatile("mma.sync.aligned.m16n8k16.row.col.f32.bf16.bf16.f32 " \
        "{%0,%1,%2,%3}, {%4,%5,%6,%7}, {%8,%9}, {%0,%1,%2,%3};" \
        : "+f"((d)[0]), "+f"((d)[1]), "+f"((d)[2]), "+f"((d)[3]) \
        : "r"((a)[0]), "r"((a)[1]), "r"((a)[2]), "r"((a)[3]), \
          "r"(b0), "r"(b1))

#define SW128(off) ((off) ^ (((off) >> 3) & 0x70))

__device__ __forceinline__ void split2(float a, float b, uint32_t& h, uint32_t& l) {
    __nv_bfloat16 ha = __float2bfloat16(a), hb = __float2bfloat16(b);
    __nv_bfloat16 la = __float2bfloat16(a - __bfloat162float(ha));
    __nv_bfloat16 lb = __float2bfloat16(b - __bfloat162float(hb));
    __nv_bfloat162 th(ha, hb), tl(la, lb);
    h = *(uint32_t*)&th; l = *(uint32_t*)&tl;
}

// ---------------------------------------------------------------------------
// fp32 -> (bf16 hi, bf16 lo) split conversion
// ---------------------------------------------------------------------------
__global__ __launch_bounds__(256) void split_bf16(
    const float* __restrict__ in, __nv_bfloat16* __restrict__ hi,
    __nv_bfloat16* __restrict__ lo, int n)
{
    int i = (blockIdx.x * 256 + threadIdx.x) * 4;
    if (i >= n) return;
    float4 v = *(const float4*)(in + i);
    uint32_t h01, l01, h23, l23;
    split2(v.x, v.y, h01, l01); split2(v.z, v.w, h23, l23);
    *(uint32_t*)(hi + i) = h01; *(uint32_t*)(hi + i + 2) = h23;
    *(uint32_t*)(lo + i) = l01; *(uint32_t*)(lo + i + 2) = l23;
}

// ---------------------------------------------------------------------------
// bf16-split GEMM on mma.sync: C[m,n] = sum_k A[m,k]*Bm[n,k] (+bias[n])
//   C = Ah*Bh + Ah*Bl + Al*Bh  (fp32 accumulate in registers)
// 128x128 CTA tile, K chunks of 64, 2-stage cp.async pipeline.
// ROUND-10: 512 threads = 16 warps in 4(m) x 4(n) grid, 32x32 per warp
// (was 8 warps x 64x32). Same swizzle/layout; ~110 regs -> 4 warps/SMSP.
// ---------------------------------------------------------------------------
#define TB_    16384
#define STAGE_ (4 * TB_)

__global__ __launch_bounds__(512) void gemm_mma(
    const __nv_bfloat16* __restrict__ Ah, const __nv_bfloat16* __restrict__ Al,
    const __nv_bfloat16* __restrict__ Bh, const __nv_bfloat16* __restrict__ Bl,
    const float* __restrict__ bias, float* __restrict__ C,
    int M, int N, int K)
{
    extern __shared__ char smem[];
    uint32_t sb = smem_u32(smem);
    int tid = threadIdx.x;
    int w = tid >> 5, lane = tid & 31;
    int bm = blockIdx.y * 128, bn = blockIdx.x * 128;
    int wm = w >> 2, wn = w & 3;     // 4x4 warps, each 32(m) x 32(n)

    const __nv_bfloat16* gsrc[4] = {
        Ah + (size_t)bm * K, Al + (size_t)bm * K,
        Bh + (size_t)bn * K, Bl + (size_t)bn * K };

    // per-thread cp.async coordinates (2 reps x 16B per matrix @512 thr)
    int lrow[2], lseg[2];
#pragma unroll
    for (int rep = 0; rep < 2; rep++) {
        int idx = rep * 512 + tid;
        lrow[rep] = idx >> 3;
        lseg[rep] = idx & 7;
    }

    float acc[2][4][4];
#pragma unroll
    for (int a = 0; a < 2; a++)
#pragma unroll
        for (int b = 0; b < 4; b++)
#pragma unroll
            for (int c = 0; c < 4; c++) acc[a][b][c] = 0.f;

    int nchunk = K >> 6;

    // prologue: stage 0 load
#pragma unroll
    for (int m = 0; m < 4; m++) {
        const __nv_bfloat16* g = gsrc[m];
        uint32_t tb = sb + m * TB_;
#pragma unroll
        for (int rep = 0; rep < 2; rep++)
            CP_ASYNC16(tb + SW128(lrow[rep] * 128 + lseg[rep] * 16),
                       g + (size_t)lrow[rep] * K + lseg[rep] * 8);
    }
    CP_COMMIT();

    for (int c = 0; c < nchunk; c++) {
        uint32_t stage = (c & 1) * STAGE_;
        if (c + 1 < nchunk) {
            int koff = (c + 1) << 6;
            uint32_t nstage = ((c + 1) & 1) * STAGE_;
#pragma unroll
            for (int m = 0; m < 4; m++) {
                const __nv_bfloat16* g = gsrc[m] + koff;
                uint32_t tb = sb + nstage + m * TB_;
#pragma unroll
                for (int rep = 0; rep < 2; rep++)
                    CP_ASYNC16(tb + SW128(lrow[rep] * 128 + lseg[rep] * 16),
                               g + (size_t)lrow[rep] * K + lseg[rep] * 8);
            }
            CP_COMMIT();
            CP_WAIT1();
        } else {
            CP_WAIT0();
        }
        __syncthreads();

        uint32_t bAh = sb + stage;
        uint32_t bAl = bAh + TB_;
        uint32_t bBh = bAl + TB_;
        uint32_t bBl = bBh + TB_;
        int rl = lane & 15, hf = lane >> 4;

#pragma unroll
        for (int k16 = 0; k16 < 4; k16++) {
            int kb = k16 * 32 + hf * 16;
            uint32_t ah[2][4], al[2][4], bh[2][4], bl[2][4];
#pragma unroll
            for (int mt = 0; mt < 2; mt++) {
                uint32_t sw = SW128((wm * 32 + mt * 16 + rl) * 128 + kb);
                LDSM4(ah[mt], bAh + sw);
                LDSM4(al[mt], bAl + sw);
            }
#pragma unroll
            for (int nt = 0; nt < 2; nt++) {
                uint32_t sw = SW128((wn * 32 + nt * 16 + rl) * 128 + kb);
                LDSM4(bh[nt], bBh + sw);
                LDSM4(bl[nt], bBl + sw);
            }
#pragma unroll
            for (int mt = 0; mt < 2; mt++)
#pragma unroll
                for (int n8 = 0; n8 < 4; n8++) {
                    int nt = n8 >> 1, sl = n8 & 1;
                    MMA16816(acc[mt][n8], ah[mt], bh[nt][sl], bh[nt][sl + 2]);
                    MMA16816(acc[mt][n8], al[mt], bh[nt][sl], bh[nt][sl + 2]);
                    MMA16816(acc[mt][n8], ah[mt], bl[nt][sl], bl[nt][sl + 2]);
                }
        }
        __syncthreads();
    }

    // Epilogue: register fragments -> gmem (float2, quad-contiguous 32B)
    int r4 = lane >> 2, c2 = (lane & 3) * 2;
#pragma unroll
    for (int mt = 0; mt < 2; mt++)
#pragma unroll
        for (int n8 = 0; n8 < 4; n8++) {
            int row = bm + wm * 32 + mt * 16 + r4;
            int col = bn + wn * 32 + n8 * 8 + c2;
            float b0 = 0.f, b1 = 0.f;
            if (bias) { b0 = bias[col]; b1 = bias[col + 1]; }
            float2 v0 = { acc[mt][n8][0] + b0, acc[mt][n8][1] + b1 };
            float2 v1 = { acc[mt][n8][2] + b0, acc[mt][n8][3] + b1 };
            *(float2*)(C + (size_t)row * N + col)       = v0;
            *(float2*)(C + (size_t)(row + 8) * N + col) = v1;
        }
}

// ---------------------------------------------------------------------------
// split_heads: g_qkv fp32 -> head-contiguous bf16 hi/lo Q, K, V^T
// grid (16 ntiles, 64 bh), 256 threads
// ---------------------------------------------------------------------------
__global__ __launch_bounds__(256) void split_heads()
{
    __shared__ float vs[64][65];
    int tid = threadIdx.x;
    int n0 = blockIdx.x * 64, bh = blockIdx.y;
    int b = bh >> 4, h = bh & 15;
    const float* src = g_qkv + ((size_t)(b * 1024) + n0) * 3072 + h * 64;
    size_t obase = ((size_t)bh * 1024 + n0) * 64;

#pragma unroll
    for (int sel = 0; sel < 2; sel++) {
        __nv_bfloat16* dh = (sel ? g_kh : g_qh) + obase;
        __nv_bfloat16* dl = (sel ? g_kl : g_ql) + obase;
#pragma unroll
        for (int rep = 0; rep < 4; rep++) {
            int i = rep * 256 + tid, row = i >> 4, d4 = (i & 15) * 4;
            float4 v = *(const float4*)(src + (size_t)row * 3072 + sel * 1024 + d4);
            uint32_t h01, l01, h23, l23;
            split2(v.x, v.y, h01, l01); split2(v.z, v.w, h23, l23);
            *(uint32_t*)(dh + row * 64 + d4)     = h01;
            *(uint32_t*)(dh + row * 64 + d4 + 2) = h23;
            *(uint32_t*)(dl + row * 64 + d4)     = l01;
            *(uint32_t*)(dl + row * 64 + d4 + 2) = l23;
        }
    }
    // V tile -> smem -> transposed split
#pragma unroll
    for (int rep = 0; rep < 4; rep++) {
        int i = rep * 256 + tid, row = i >> 4, d4 = (i & 15) * 4;
        float4 v = *(const float4*)(src + (size_t)row * 3072 + 2048 + d4);
        vs[row][d4] = v.x; vs[row][d4 + 1] = v.y;
        vs[row][d4 + 2] = v.z; vs[row][d4 + 3] = v.w;
    }
    __syncthreads();
#pragma unroll
    for (int rep = 0; rep < 4; rep++) {
        int i = rep * 256 + tid, d = i >> 4, m4 = (i & 15) * 4;
        float x0 = vs[m4][d], x1 = vs[m4 + 1][d], x2 = vs[m4 + 2][d], x3 = vs[m4 + 3][d];
        uint32_t h01, l01, h23, l23;
        split2(x0, x1, h01, l01); split2(x2, x3, h23, l23);
        __nv_bfloat16* dh = g_vth + ((size_t)bh * 64 + d) * 1024 + n0 + m4;
        __nv_bfloat16* dl = g_vtl + ((size_t)bh * 64 + d) * 1024 + n0 + m4;
        *(uint32_t*)dh = h01; *(uint32_t*)(dh + 2) = h23;
        *(uint32_t*)dl = l01; *(uint32_t*)(dl + 2) = l23;
    }
}

// ---------------------------------------------------------------------------
// attn_mma: causal relative flash-attention on mma.sync (bf16 split)
// (unchanged from round-9 passing version)
// ---------------------------------------------------------------------------
#define ASMEM_ 198656

__global__ __launch_bounds__(256, 1) void attn_mma()
{
    extern __shared__ char smem[];
    uint32_t sb = smem_u32(smem);
    const int tid = threadIdx.x, w = tid >> 5, lane = tid & 31;
    const int wm = w & 3, wn = w >> 2;
    const int n0 = blockIdx.x * 64, bh = blockIdx.y;
    const int rl = lane & 15, hf = lane >> 4;
    const int r4 = lane >> 2, c2 = (lane & 3) * 2;

    const uint32_t sQh = sb, sQl = sb + 8192;
    float* Rsm  = (float*)(smem + 147456);          // pitch 132 floats
    float* redA = (float*)(smem + 197632);          // [64][2] row max
    float* redB = (float*)(smem + 198144);          // [64][2] row sum

    // ---- Q tile load (once)
    {
        const __nv_bfloat16* qh = g_qh + ((size_t)bh * 1024 + n0) * 64;
        const __nv_bfloat16* ql = g_ql + ((size_t)bh * 1024 + n0) * 64;
#pragma unroll
        for (int rep = 0; rep < 2; rep++) {
            int i = rep * 256 + tid, row = i >> 3, seg = i & 7;
            uint32_t sw = SW128(row * 128 + seg * 16);
            CP_ASYNC16(sQh + sw, qh + (size_t)row * 64 + seg * 8);
            CP_ASYNC16(sQl + sw, ql + (size_t)row * 64 + seg * 8);
        }
    }

    // ---- stage loader (K,V^T,E band for key tile m0)
    auto load_stage = [&](int s, int m0) {
        uint32_t st = sb + 16384 + s * 65536;
        const __nv_bfloat16* kh = g_kh + ((size_t)bh * 1024 + m0) * 64;
        const __nv_bfloat16* kl = g_kl + ((size_t)bh * 1024 + m0) * 64;
#pragma unroll
        for (int rep = 0; rep < 2; rep++) {
            int i = rep * 256 + tid, row = i >> 3, seg = i & 7;
            uint32_t sw = SW128(row * 128 + seg * 16);
            CP_ASYNC16(st + sw,        kh + (size_t)row * 64 + seg * 8);
            CP_ASYNC16(st + 8192 + sw, kl + (size_t)row * 64 + seg * 8);
        }
#pragma unroll
        for (int rep = 0; rep < 2; rep++) {
            int i = rep * 256 + tid, row = i >> 3, seg = i & 7;
            uint32_t sw = SW128(row * 128 + seg * 16);
            CP_ASYNC16(st + 16384 + sw,
                       g_vth + ((size_t)bh * 64 + row) * 1024 + m0 + seg * 8);
            CP_ASYNC16(st + 24576 + sw,
                       g_vtl + ((size_t)bh * 64 + row) * 1024 + m0 + seg * 8);
        }
        int ebase = 960 - n0 + m0;
#pragma unroll
        for (int rep = 0; rep < 4; rep++) {
            int i = rep * 256 + tid, row = i >> 3, seg = i & 7;
            int er = ebase + row; if (er > 1023) er = 1023;
            uint32_t sw = SW128(row * 128 + seg * 16);
            CP_ASYNC16(st + 32768 + sw, g_erh + (size_t)er * 64 + seg * 8);
            CP_ASYNC16(st + 49152 + sw, g_erl + (size_t)er * 64 + seg * 8);
        }
    };

    float O[4][4];
#pragma unroll
    for (int a = 0; a < 4; a++)
#pragma unroll
        for (int c = 0; c < 4; c++) O[a][c] = 0.f;
    float Mx[2] = { -3.0e38f, -3.0e38f }, Lx[2] = { 0.f, 0.f };

    load_stage(0, 0);
    CP_COMMIT();

    const int nit = (n0 >> 6) + 1;
    for (int it = 0; it < nit; it++) {
        if (it + 1 < nit) { load_stage((it + 1) & 1, (it + 1) * 64); CP_COMMIT(); CP_WAIT1(); }
        else              { CP_WAIT0(); }
        __syncthreads();

        uint32_t st = sb + 16384 + (it & 1) * 65536;

        // ---- content (Sc 64x64) + rel (Sr 64x128) MMAs
        float Sc[4][4], Sr[8][4];
#pragma unroll
        for (int a = 0; a < 4; a++)
#pragma unroll
            for (int c = 0; c < 4; c++) Sc[a][c] = 0.f;
#pragma unroll
        for (int a = 0; a < 8; a++)
#pragma unroll
            for (int c = 0; c < 4; c++) Sr[a][c] = 0.f;

#pragma unroll
        for (int k16 = 0; k16 < 4; k16++) {
            int kb = k16 * 32 + hf * 16;
            uint32_t aqh[4], aql[4];
            uint32_t swA = SW128((wm * 16 + rl) * 128 + kb);
            LDSM4(aqh, sQh + swA);
            LDSM4(aql, sQl + swA);
            uint32_t bkh[2][4], bkl[2][4];
#pragma unroll
            for (int nt = 0; nt < 2; nt++) {
                uint32_t sw = SW128((wn * 32 + nt * 16 + rl) * 128 + kb);
                LDSM4(bkh[nt], st + sw);
                LDSM4(bkl[nt], st + 8192 + sw);
            }
#pragma unroll
            for (int n8 = 0; n8 < 4; n8++) {
                int nt = n8 >> 1, sl = n8 & 1;
                MMA16816(Sc[n8], aqh, bkh[nt][sl], bkh[nt][sl + 2]);
                MMA16816(Sc[n8], aql, bkh[nt][sl], bkh[nt][sl + 2]);
                MMA16816(Sc[n8], aqh, bkl[nt][sl], bkl[nt][sl + 2]);
            }
            uint32_t beh[4][4], bel[4][4];
#pragma unroll
            for (int nt = 0; nt < 4; nt++) {
                uint32_t sw = SW128((wn * 64 + nt * 16 + rl) * 128 + kb);
                LDSM4(beh[nt], st + 32768 + sw);
                LDSM4(bel[nt], st + 49152 + sw);
            }
#pragma unroll
            for (int n8 = 0; n8 < 8; n8++) {
                int nt = n8 >> 1, sl = n8 & 1;
                MMA16816(Sr[n8], aqh, beh[nt][sl], beh[nt][sl + 2]);
                MMA16816(Sr[n8], aql, beh[nt][sl], beh[nt][sl + 2]);
                MMA16816(Sr[n8], aqh, bel[nt][sl], bel[nt][sl + 2]);
            }
        }

        // ---- stage rel to SMEM (fp32 [64][132])
        {
            int i0 = wm * 16 + r4;
#pragma unroll
            for (int n8 = 0; n8 < 8; n8++) {
                int u = wn * 64 + n8 * 8 + c2;
                *(float2*)(Rsm + (size_t)i0 * 132 + u)       = make_float2(Sr[n8][0], Sr[n8][1]);
                *(float2*)(Rsm + (size_t)(i0 + 8) * 132 + u) = make_float2(Sr[n8][2], Sr[n8][3]);
            }
        }
        __syncthreads();

        // ---- gather rel diagonal band + scale + causal mask
        const bool diag = (it == nit - 1);
        int i0 = wm * 16 + r4, i1 = i0 + 8;
#pragma unroll
        for (int n8 = 0; n8 < 4; n8++) {
            int j = wn * 32 + n8 * 8 + c2;
            Sc[n8][0] = (Sc[n8][0] + Rsm[(size_t)i0 * 132 + (j     - i0 + 63)]) * 0.125f;
            Sc[n8][1] = (Sc[n8][1] + Rsm[(size_t)i0 * 132 + (j + 1 - i0 + 63)]) * 0.125f;
            Sc[n8][2] = (Sc[n8][2] + Rsm[(size_t)i1 * 132 + (j     - i1 + 63)]) * 0.125f;
            Sc[n8][3] = (Sc[n8][3] + Rsm[(size_t)i1 * 132 + (j + 1 - i1 + 63)]) * 0.125f;
            if (diag) {
                if (j     > i0) Sc[n8][0] = -1.0e30f;
                if (j + 1 > i0) Sc[n8][1] = -1.0e30f;
                if (j     > i1) Sc[n8][2] = -1.0e30f;
                if (j + 1 > i1) Sc[n8][3] = -1.0e30f;
            }
        }

        // ---- row max (quad shuffle + cross-warp SMEM exchange)
        float m0_ = -3.0e38f, m1_ = -3.0e38f;
#pragma unroll
        for (int n8 = 0; n8 < 4; n8++) {
            m0_ = fmaxf(m0_, fmaxf(Sc[n8][0], Sc[n8][1]));
            m1_ = fmaxf(m1_, fmaxf(Sc[n8][2], Sc[n8][3]));
        }
        m0_ = fmaxf(m0_, __shfl_xor_sync(0xffffffffu, m0_, 1));
        m0_ = fmaxf(m0_, __shfl_xor_sync(0xffffffffu, m0_, 2));
        m1_ = fmaxf(m1_, __shfl_xor_sync(0xffffffffu, m1_, 1));
        m1_ = fmaxf(m1_, __shfl_xor_sync(0xffffffffu, m1_, 2));
        if ((lane & 3) == 0) {
            redA[i0 * 2 + wn] = m0_;
            redA[i1 * 2 + wn] = m1_;
        }
        __syncthreads();
        m0_ = fmaxf(redA[i0 * 2], redA[i0 * 2 + 1]);
        m1_ = fmaxf(redA[i1 * 2], redA[i1 * 2 + 1]);

        float mn0 = fmaxf(Mx[0], m0_), mn1 = fmaxf(Mx[1], m1_);
        float al0 = __expf(Mx[0] - mn0), al1 = __expf(Mx[1] - mn1);

        // ---- exp + row sum
        float s0 = 0.f, s1 = 0.f;
#pragma unroll
        for (int n8 = 0; n8 < 4; n8++) {
            Sc[n8][0] = __expf(Sc[n8][0] - mn0);
            Sc[n8][1] = __expf(Sc[n8][1] - mn0);
            Sc[n8][2] = __expf(Sc[n8][2] - mn1);
            Sc[n8][3] = __expf(Sc[n8][3] - mn1);
            s0 += Sc[n8][0] + Sc[n8][1];
            s1 += Sc[n8][2] + Sc[n8][3];
        }
        s0 += __shfl_xor_sync(0xffffffffu, s0, 1);
        s0 += __shfl_xor_sync(0xffffffffu, s0, 2);
        s1 += __shfl_xor_sync(0xffffffffu, s1, 1);
        s1 += __shfl_xor_sync(0xffffffffu, s1, 2);
        if ((lane & 3) == 0) {
            redB[i0 * 2 + wn] = s0;
            redB[i1 * 2 + wn] = s1;
        }
        __syncthreads();
        s0 = redB[i0 * 2] + redB[i0 * 2 + 1];
        s1 = redB[i1 * 2] + redB[i1 * 2 + 1];

        Lx[0] = Lx[0] * al0 + s0; Mx[0] = mn0;
        Lx[1] = Lx[1] * al1 + s1; Mx[1] = mn1;
#pragma unroll
        for (int n8 = 0; n8 < 4; n8++) {
            O[n8][0] *= al0; O[n8][1] *= al0;
            O[n8][2] *= al1; O[n8][3] *= al1;
        }

        // ---- P -> SMEM (bf16 split, swizzled rows i x 64 cols)
#pragma unroll
        for (int n8 = 0; n8 < 4; n8++) {
            int jb = (wn * 32 + n8 * 8 + c2) * 2;   // byte col offset
            uint32_t h01, l01, h23, l23;
            split2(Sc[n8][0], Sc[n8][1], h01, l01);
            split2(Sc[n8][2], Sc[n8][3], h23, l23);
            uint32_t o0 = SW128(i0 * 128 + jb), o1 = SW128(i1 * 128 + jb);
            *(uint32_t*)(smem + 181248 + o0) = h01;
            *(uint32_t*)(smem + 189440 + o0) = l01;
            *(uint32_t*)(smem + 181248 + o1) = h23;
            *(uint32_t*)(smem + 189440 + o1) = l23;
        }
        __syncthreads();

        // ---- P @ V^T  (A = P rows, B = Vt rows d, k = keys)
#pragma unroll
        for (int k16 = 0; k16 < 4; k16++) {
            int kb = k16 * 32 + hf * 16;
            uint32_t aph[4], apl[4];
            uint32_t swA = SW128((wm * 16 + rl) * 128 + kb);
            LDSM4(aph, sb + 181248 + swA);
            LDSM4(apl, sb + 189440 + swA);
            uint32_t bvh[2][4], bvl[2][4];
#pragma unroll
            for (int nt = 0; nt < 2; nt++) {
                uint32_t sw = SW128((wn * 32 + nt * 16 + rl) * 128 + kb);
                LDSM4(bvh[nt], st + 16384 + sw);
                LDSM4(bvl[nt], st + 24576 + sw);
            }
#pragma unroll
            for (int n8 = 0; n8 < 4; n8++) {
                int nt = n8 >> 1, sl = n8 & 1;
                MMA16816(O[n8], aph, bvh[nt][sl], bvh[nt][sl + 2]);
                MMA16816(O[n8], apl, bvh[nt][sl], bvh[nt][sl + 2]);
                MMA16816(O[n8], aph, bvl[nt][sl], bvl[nt][sl + 2]);
            }
        }
        __syncthreads();   // protect stage/P/R reuse next iteration
    }

    // ---- normalize + write out: g_attn[b][n0+i][h*64 + d]
    {
        int b = bh >> 4, h = bh & 15;
        float inv0 = 1.0f / Lx[0], inv1 = 1.0f / Lx[1];
        float* op = g_attn + ((size_t)(b * 1024) + n0) * 1024 + h * 64;
        int i0 = wm * 16 + r4;
#pragma unroll
        for (int n8 = 0; n8 < 4; n8++) {
            int col = wn * 32 + n8 * 8 + c2;
            *(float2*)(op + (size_t)i0 * 1024 + col) =
                make_float2(O[n8][0] * inv0, O[n8][1] * inv0);
            *(float2*)(op + (size_t)(i0 + 8) * 1024 + col) =
                make_float2(O[n8][2] * inv1, O[n8][3] * inv1);
        }
    }
}

// ---------------------------------------------------------------------------
extern "C" void kernel_launch(void* const* d_in, const int* in_sizes, int n_in,
                              void* d_out, int out_size)
{
    const float* x      = (const float*)d_in[0];
    const float* W_qkv  = (const float*)d_in[1];
    const float* W_proj = (const float*)d_in[2];
    const float* b_proj = (const float*)d_in[3];
    const float* Er     = (const float*)d_in[4];
    float* out = (float*)d_out;

    float *qkv, *attn;
    __nv_bfloat16 *ah, *al, *wh, *wl, *ph, *pl, *erh, *erl;
    cudaGetSymbolAddress((void**)&qkv, g_qkv);
    cudaGetSymbolAddress((void**)&attn, g_attn);
    cudaGetSymbolAddress((void**)&ah, g_ah);
    cudaGetSymbolAddress((void**)&al, g_al);
    cudaGetSymbolAddress((void**)&wh, g_wh);
    cudaGetSymbolAddress((void**)&wl, g_wl);
    cudaGetSymbolAddress((void**)&ph, g_ph);
    cudaGetSymbolAddress((void**)&pl, g_pl);
    cudaGetSymbolAddress((void**)&erh, g_erh);
    cudaGetSymbolAddress((void**)&erl, g_erl);

    int gemm_smem = 2 * STAGE_;   // 128 KB
    cudaFuncSetAttribute(gemm_mma, cudaFuncAttributeMaxDynamicSharedMemorySize, gemm_smem);
    cudaFuncSetAttribute(attn_mma, cudaFuncAttributeMaxDynamicSharedMemorySize, ASMEM_);

    int n_x  = ROWS_ * DIM_;
    int n_wq = 3 * DIM_ * DIM_;
    int n_wp = DIM_ * DIM_;

    split_bf16<<<n_x  / 1024, 256>>>(x,      ah, al, n_x);
    split_bf16<<<n_wq / 1024, 256>>>(W_qkv,  wh, wl, n_wq);
    split_bf16<<<n_wp / 1024, 256>>>(W_proj, ph, pl, n_wp);
    split_bf16<<<64, 256>>>(Er, erh, erl, 1024 * 64);

    // 1) QKV projection
    gemm_mma<<<dim3(3 * DIM_ / 128, ROWS_ / 128), 512, gemm_smem>>>(
        ah, al, wh, wl, nullptr, qkv, ROWS_, 3 * DIM_, DIM_);

    // 2) head split + tensor-core attention
    split_heads<<<dim3(16, 64), 256>>>();
    attn_mma<<<dim3(16, 64), 256, ASMEM_>>>();

    // 3) output projection
    split_bf16<<<n_x / 1024, 256>>>(attn, ah, al, n_x);
    gemm_mma<<<dim3(DIM_ / 128, ROWS_ / 128), 512, gemm_smem>>>(
        ah, al, ph, pl, b_proj, out, ROWS_, DIM_, DIM_);
}

// round 12
// speedup vs baseline: 2.5984x; 1.0409x over previous
#include <cuda_runtime.h>
#include <cuda_bf16.h>
#include <math.h>
#include <stdint.h>

#define B_    4
#define N_    1024
#define DIM_  1024
#define H_    16
#define HD_   64
#define ROWS_ (B_ * N_)          // 4096

// ---------------------------------------------------------------------------
// Scratch (device globals: allocation-free rule)
// ---------------------------------------------------------------------------
__device__ __nv_bfloat16 g_ah[(size_t)ROWS_ * DIM_];       // x / attn-out hi
__device__ __nv_bfloat16 g_al[(size_t)ROWS_ * DIM_];       // x / attn-out lo
__device__ __nv_bfloat16 g_wh[(size_t)3 * DIM_ * DIM_];    // W_qkv hi
__device__ __nv_bfloat16 g_wl[(size_t)3 * DIM_ * DIM_];    // W_qkv lo
__device__ __nv_bfloat16 g_ph[(size_t)DIM_ * DIM_];        // W_proj hi
__device__ __nv_bfloat16 g_pl[(size_t)DIM_ * DIM_];        // W_proj lo
// head-contiguous split buffers for attention  [bh][n][d] / [bh][d][n]
__device__ __nv_bfloat16 g_qh[(size_t)64 * 1024 * 64];
__device__ __nv_bfloat16 g_ql[(size_t)64 * 1024 * 64];
__device__ __nv_bfloat16 g_kh[(size_t)64 * 1024 * 64];
__device__ __nv_bfloat16 g_kl[(size_t)64 * 1024 * 64];
__device__ __nv_bfloat16 g_vth[(size_t)64 * 64 * 1024];    // V^T
__device__ __nv_bfloat16 g_vtl[(size_t)64 * 64 * 1024];
__device__ __nv_bfloat16 g_erh[(size_t)1024 * 64];
__device__ __nv_bfloat16 g_erl[(size_t)1024 * 64];

// ---------------------------------------------------------------------------
// Portable PTX helpers (sm_80+ family-generic)
// ---------------------------------------------------------------------------
__device__ __forceinline__ uint32_t smem_u32(const void* p) {
    uint32_t a;
    asm("{ .reg .u64 t; cvta.to.shared.u64 t, %1; cvt.u32.u64 %0, t; }"
        : "=r"(a) : "l"(p));
    return a;
}

#define CP_ASYNC16(saddr, gptr) \
    asm volatile("cp.async.cg.shared.global [%0], [%1], 16;" \
        :: "r"(saddr), "l"(gptr) : "memory")
#define CP_COMMIT() asm volatile("cp.async.commit_group;" ::: "memory")
#define CP_WAIT1()  asm volatile("cp.async.wait_group 1;" ::: "memory")
#define CP_WAIT0()  asm volatile("cp.async.wait_group 0;" ::: "memory")

#define LDSM4(r, addr) \
    asm volatile("ldmatrix.sync.aligned.m8n8.x4.shared.b16 {%0,%1,%2,%3}, [%4];" \
        : "=r"((r)[0]), "=r"((r)[1]), "=r"((r)[2]), "=r"((r)[3]) : "r"(addr))

#define MMA16816(d, a, b0, b1) \
    asm volatile("mma.sync.aligned.m16n8k16.row.col.f32.bf16.bf16.f32 " \
        "{%0,%1,%2,%3}, {%4,%5,%6,%7}, {%8,%9}, {%0,%1,%2,%3};" \
        : "+f"((d)[0]), "+f"((d)[1]), "+f"((d)[2]), "+f"((d)[3]) \
        : "r"((a)[0]), "r"((a)[1]), "r"((a)[2]), "r"((a)[3]), \
          "r"(b0), "r"(b1))

#define SW128(off) ((off) ^ (((off) >> 3) & 0x70))

__device__ __forceinline__ void split2(float a, float b, uint32_t& h, uint32_t& l) {
    __nv_bfloat16 ha = __float2bfloat16(a), hb = __float2bfloat16(b);
    __nv_bfloat16 la = __float2bfloat16(a - __bfloat162float(ha));
    __nv_bfloat16 lb = __float2bfloat16(b - __bfloat162float(hb));
    __nv_bfloat162 th(ha, hb), tl(la, lb);
    h = *(uint32_t*)&th; l = *(uint32_t*)&tl;
}

// ---------------------------------------------------------------------------
// fp32 -> (bf16 hi, bf16 lo) split conversion
// ---------------------------------------------------------------------------
__global__ __launch_bounds__(256) void split_bf16(
    const float* __restrict__ in, __nv_bfloat16* __restrict__ hi,
    __nv_bfloat16* __restrict__ lo, int n)
{
    int i = (blockIdx.x * 256 + threadIdx.x) * 4;
    if (i >= n) return;
    float4 v = *(const float4*)(in + i);
    uint32_t h01, l01, h23, l23;
    split2(v.x, v.y, h01, l01); split2(v.z, v.w, h23, l23);
    *(uint32_t*)(hi + i) = h01; *(uint32_t*)(hi + i + 2) = h23;
    *(uint32_t*)(lo + i) = l01; *(uint32_t*)(lo + i + 2) = l23;
}

// ---------------------------------------------------------------------------
// Shared GEMM mainloop (bf16-split, 512 thr, 128x128 tile, 2-stage cp.async).
// acc layout: warp (wm,wn) owns 32x32; acc[mt][n8] fragment rows
// {wm*32+mt*16+r4, +8}, cols {wn*32+n8*8+c2, +1}.
// ---------------------------------------------------------------------------
#define TB_    16384
#define STAGE_ (4 * TB_)

#define GEMM_MAINLOOP(Ah_, Al_, Bh_, Bl_, Kdim)                                   \
    const __nv_bfloat16* gsrc[4] = {                                              \
        (Ah_) + (size_t)bm * (Kdim), (Al_) + (size_t)bm * (Kdim),                 \
        (Bh_) + (size_t)bn * (Kdim), (Bl_) + (size_t)bn * (Kdim) };               \
    int lrow[2], lseg[2];                                                         \
    _Pragma("unroll")                                                             \
    for (int rep = 0; rep < 2; rep++) {                                           \
        int idx = rep * 512 + tid;                                                \
        lrow[rep] = idx >> 3;                                                     \
        lseg[rep] = idx & 7;                                                      \
    }                                                                             \
    _Pragma("unroll")                                                             \
    for (int a = 0; a < 2; a++)                                                   \
        _Pragma("unroll")                                                         \
        for (int b = 0; b < 4; b++)                                               \
            _Pragma("unroll")                                                     \
            for (int c = 0; c < 4; c++) acc[a][b][c] = 0.f;                       \
    int nchunk = (Kdim) >> 6;                                                     \
    _Pragma("unroll")                                                             \
    for (int m = 0; m < 4; m++) {                                                 \
        const __nv_bfloat16* g = gsrc[m];                                         \
        uint32_t tb = sb + m * TB_;                                               \
        _Pragma("unroll")                                                         \
        for (int rep = 0; rep < 2; rep++)                                         \
            CP_ASYNC16(tb + SW128(lrow[rep] * 128 + lseg[rep] * 16),              \
                       g + (size_t)lrow[rep] * (Kdim) + lseg[rep] * 8);           \
    }                                                                             \
    CP_COMMIT();                                                                  \
    for (int c = 0; c < nchunk; c++) {                                            \
        uint32_t stage = (c & 1) * STAGE_;                                        \
        if (c + 1 < nchunk) {                                                     \
            int koff = (c + 1) << 6;                                              \
            uint32_t nstage = ((c + 1) & 1) * STAGE_;                             \
            _Pragma("unroll")                                                     \
            for (int m = 0; m < 4; m++) {                                         \
                const __nv_bfloat16* g = gsrc[m] + koff;                          \
                uint32_t tb = sb + nstage + m * TB_;                              \
                _Pragma("unroll")                                                 \
                for (int rep = 0; rep < 2; rep++)                                 \
                    CP_ASYNC16(tb + SW128(lrow[rep] * 128 + lseg[rep] * 16),      \
                               g + (size_t)lrow[rep] * (Kdim) + lseg[rep] * 8);   \
            }                                                                     \
            CP_COMMIT();                                                          \
            CP_WAIT1();                                                           \
        } else {                                                                  \
            CP_WAIT0();                                                           \
        }                                                                         \
        __syncthreads();                                                          \
        uint32_t bAh = sb + stage;                                                \
        uint32_t bAl = bAh + TB_;                                                 \
        uint32_t bBh = bAl + TB_;                                                 \
        uint32_t bBl = bBh + TB_;                                                 \
        _Pragma("unroll")                                                         \
        for (int k16 = 0; k16 < 4; k16++) {                                       \
            int kb = k16 * 32 + hf * 16;                                          \
            uint32_t ah[2][4], al[2][4], bh[2][4], bl[2][4];                      \
            _Pragma("unroll")                                                     \
            for (int mt = 0; mt < 2; mt++) {                                      \
                uint32_t sw = SW128((wm * 32 + mt * 16 + rl) * 128 + kb);         \
                LDSM4(ah[mt], bAh + sw);                                          \
                LDSM4(al[mt], bAl + sw);                                          \
            }                                                                     \
            _Pragma("unroll")                                                     \
            for (int nt = 0; nt < 2; nt++) {                                      \
                uint32_t sw = SW128((wn * 32 + nt * 16 + rl) * 128 + kb);         \
                LDSM4(bh[nt], bBh + sw);                                          \
                LDSM4(bl[nt], bBl + sw);                                          \
            }                                                                     \
            _Pragma("unroll")                                                     \
            for (int mt = 0; mt < 2; mt++)                                        \
                _Pragma("unroll")                                                 \
                for (int n8 = 0; n8 < 4; n8++) {                                  \
                    int nt = n8 >> 1, sl = n8 & 1;                                \
                    MMA16816(acc[mt][n8], ah[mt], bh[nt][sl], bh[nt][sl + 2]);    \
                    MMA16816(acc[mt][n8], al[mt], bh[nt][sl], bh[nt][sl + 2]);    \
                    MMA16816(acc[mt][n8], ah[mt], bl[nt][sl], bl[nt][sl + 2]);    \
                }                                                                 \
        }                                                                         \
        __syncthreads();                                                          \
    }

// ---------------------------------------------------------------------------
// gemm_proj: generic C = A*B^T + bias, fp32 output (used for out projection)
// ---------------------------------------------------------------------------
__global__ __launch_bounds__(512) void gemm_proj(
    const __nv_bfloat16* __restrict__ Ah, const __nv_bfloat16* __restrict__ Al,
    const __nv_bfloat16* __restrict__ Bh, const __nv_bfloat16* __restrict__ Bl,
    const float* __restrict__ bias, float* __restrict__ C,
    int M, int N, int K)
{
    extern __shared__ char smem[];
    uint32_t sb = smem_u32(smem);
    int tid = threadIdx.x;
    int w = tid >> 5, lane = tid & 31;
    int bm = blockIdx.y * 128, bn = blockIdx.x * 128;
    int wm = w >> 2, wn = w & 3;
    int rl = lane & 15, hf = lane >> 4;
    float acc[2][4][4];

    GEMM_MAINLOOP(Ah, Al, Bh, Bl, K)

    int r4 = lane >> 2, c2 = (lane & 3) * 2;
#pragma unroll
    for (int mt = 0; mt < 2; mt++)
#pragma unroll
        for (int n8 = 0; n8 < 4; n8++) {
            int row = bm + wm * 32 + mt * 16 + r4;
            int col = bn + wn * 32 + n8 * 8 + c2;
            float b0 = bias[col], b1 = bias[col + 1];
            float2 v0 = { acc[mt][n8][0] + b0, acc[mt][n8][1] + b1 };
            float2 v1 = { acc[mt][n8][2] + b0, acc[mt][n8][3] + b1 };
            *(float2*)(C + (size_t)row * N + col)       = v0;
            *(float2*)(C + (size_t)(row + 8) * N + col) = v1;
        }
}

// ---------------------------------------------------------------------------
// gemm_qkv: QKV projection with FUSED head-split epilogue.
// Writes bf16 hi/lo directly: Q,K -> [bh][n][d]; V -> transposed [bh][d][n]
// via SMEM staging. Eliminates g_qkv fp32 intermediate + split_heads kernel.
// ---------------------------------------------------------------------------
__global__ __launch_bounds__(512) void gemm_qkv(
    const __nv_bfloat16* __restrict__ Ah, const __nv_bfloat16* __restrict__ Al,
    const __nv_bfloat16* __restrict__ Bh, const __nv_bfloat16* __restrict__ Bl,
    int K)
{
    extern __shared__ char smem[];
    uint32_t sb = smem_u32(smem);
    int tid = threadIdx.x;
    int w = tid >> 5, lane = tid & 31;
    int bm = blockIdx.y * 128, bn = blockIdx.x * 128;
    int wm = w >> 2, wn = w & 3;
    int rl = lane & 15, hf = lane >> 4;
    float acc[2][4][4];

    GEMM_MAINLOOP(Ah, Al, Bh, Bl, K)

    int r4 = lane >> 2, c2 = (lane & 3) * 2;
    int qsel = bn >> 10;          // 0=q 1=k 2=v
    int cin  = bn & 1023;         // col within region (multiple of 128)
    int b    = bm >> 10;
    int nb   = bm & 1023;

    if (qsel < 2) {
        __nv_bfloat16* dh = qsel ? g_kh : g_qh;
        __nv_bfloat16* dl = qsel ? g_kl : g_ql;
#pragma unroll
        for (int mt = 0; mt < 2; mt++)
#pragma unroll
            for (int n8 = 0; n8 < 4; n8++) {
                int row = wm * 32 + mt * 16 + r4;
                int ch  = cin + wn * 32 + n8 * 8 + c2;
                size_t base = ((size_t)(b * 16 + (ch >> 6)) * 1024 + nb) * 64
                            + (ch & 63);
                uint32_t h01, l01, h23, l23;
                split2(acc[mt][n8][0], acc[mt][n8][1], h01, l01);
                split2(acc[mt][n8][2], acc[mt][n8][3], h23, l23);
                *(uint32_t*)(dh + base + (size_t)row * 64)       = h01;
                *(uint32_t*)(dl + base + (size_t)row * 64)       = l01;
                *(uint32_t*)(dh + base + (size_t)(row + 8) * 64) = h23;
                *(uint32_t*)(dl + base + (size_t)(row + 8) * 64) = l23;
            }
    } else {
        // V: stage transposed [col][row] in SMEM (pitch 132), then coalesced
        // split-writes along n into g_vth/g_vtl.
        float* stage = (float*)smem;
#pragma unroll
        for (int mt = 0; mt < 2; mt++)
#pragma unroll
            for (int n8 = 0; n8 < 4; n8++) {
                int row = wm * 32 + mt * 16 + r4;
                int col = wn * 32 + n8 * 8 + c2;
                stage[(col    ) * 132 + row    ] = acc[mt][n8][0];
                stage[(col + 1) * 132 + row    ] = acc[mt][n8][1];
                stage[(col    ) * 132 + row + 8] = acc[mt][n8][2];
                stage[(col + 1) * 132 + row + 8] = acc[mt][n8][3];
            }
        __syncthreads();
#pragma unroll
        for (int cc = 0; cc < 8; cc++) {
            int c  = cc * 16 + w;
            int ch = cin + c;
            size_t dst = ((size_t)(b * 16 + (ch >> 6)) * 64 + (ch & 63)) * 1024 + nb;
#pragma unroll
            for (int p = 0; p < 2; p++) {
                int n = p * 64 + lane * 2;
                float2 v = *(float2*)&stage[c * 132 + n];
                uint32_t hh, ll;
                split2(v.x, v.y, hh, ll);
                *(uint32_t*)(g_vth + dst + n) = hh;
                *(uint32_t*)(g_vtl + dst + n) = ll;
            }
        }
    }
}

// ---------------------------------------------------------------------------
// attn_mma: causal relative flash-attention on mma.sync (bf16 split)
// R12: epilogue writes split bf16 (g_ah/g_al) directly for the proj GEMM.
// ---------------------------------------------------------------------------
#define ASMEM_ 198656

__global__ __launch_bounds__(256, 1) void attn_mma()
{
    extern __shared__ char smem[];
    uint32_t sb = smem_u32(smem);
    const int tid = threadIdx.x, w = tid >> 5, lane = tid & 31;
    const int wm = w & 3, wn = w >> 2;
    const int n0 = blockIdx.x * 64, bh = blockIdx.y;
    const int rl = lane & 15, hf = lane >> 4;
    const int r4 = lane >> 2, c2 = (lane & 3) * 2;

    const uint32_t sQh = sb, sQl = sb + 8192;
    float* Rsm  = (float*)(smem + 147456);          // pitch 132 floats
    float* redA = (float*)(smem + 197632);          // [64][2] row max
    float* redB = (float*)(smem + 198144);          // [64][2] row sum

    // ---- Q tile load (once)
    {
        const __nv_bfloat16* qh = g_qh + ((size_t)bh * 1024 + n0) * 64;
        const __nv_bfloat16* ql = g_ql + ((size_t)bh * 1024 + n0) * 64;
#pragma unroll
        for (int rep = 0; rep < 2; rep++) {
            int i = rep * 256 + tid, row = i >> 3, seg = i & 7;
            uint32_t sw = SW128(row * 128 + seg * 16);
            CP_ASYNC16(sQh + sw, qh + (size_t)row * 64 + seg * 8);
            CP_ASYNC16(sQl + sw, ql + (size_t)row * 64 + seg * 8);
        }
    }

    // ---- stage loader (K,V^T,E band for key tile m0)
    auto load_stage = [&](int s, int m0) {
        uint32_t st = sb + 16384 + s * 65536;
        const __nv_bfloat16* kh = g_kh + ((size_t)bh * 1024 + m0) * 64;
        const __nv_bfloat16* kl = g_kl + ((size_t)bh * 1024 + m0) * 64;
#pragma unroll
        for (int rep = 0; rep < 2; rep++) {
            int i = rep * 256 + tid, row = i >> 3, seg = i & 7;
            uint32_t sw = SW128(row * 128 + seg * 16);
            CP_ASYNC16(st + sw,        kh + (size_t)row * 64 + seg * 8);
            CP_ASYNC16(st + 8192 + sw, kl + (size_t)row * 64 + seg * 8);
        }
#pragma unroll
        for (int rep = 0; rep < 2; rep++) {
            int i = rep * 256 + tid, row = i >> 3, seg = i & 7;
            uint32_t sw = SW128(row * 128 + seg * 16);
            CP_ASYNC16(st + 16384 + sw,
                       g_vth + ((size_t)bh * 64 + row) * 1024 + m0 + seg * 8);
            CP_ASYNC16(st + 24576 + sw,
                       g_vtl + ((size_t)bh * 64 + row) * 1024 + m0 + seg * 8);
        }
        int ebase = 960 - n0 + m0;
#pragma unroll
        for (int rep = 0; rep < 4; rep++) {
            int i = rep * 256 + tid, row = i >> 3, seg = i & 7;
            int er = ebase + row; if (er > 1023) er = 1023;
            uint32_t sw = SW128(row * 128 + seg * 16);
            CP_ASYNC16(st + 32768 + sw, g_erh + (size_t)er * 64 + seg * 8);
            CP_ASYNC16(st + 49152 + sw, g_erl + (size_t)er * 64 + seg * 8);
        }
    };

    float O[4][4];
#pragma unroll
    for (int a = 0; a < 4; a++)
#pragma unroll
        for (int c = 0; c < 4; c++) O[a][c] = 0.f;
    float Mx[2] = { -3.0e38f, -3.0e38f }, Lx[2] = { 0.f, 0.f };

    load_stage(0, 0);
    CP_COMMIT();

    const int nit = (n0 >> 6) + 1;
    for (int it = 0; it < nit; it++) {
        if (it + 1 < nit) { load_stage((it + 1) & 1, (it + 1) * 64); CP_COMMIT(); CP_WAIT1(); }
        else              { CP_WAIT0(); }
        __syncthreads();

        uint32_t st = sb + 16384 + (it & 1) * 65536;

        // ---- content (Sc 64x64) + rel (Sr 64x128) MMAs
        float Sc[4][4], Sr[8][4];
#pragma unroll
        for (int a = 0; a < 4; a++)
#pragma unroll
            for (int c = 0; c < 4; c++) Sc[a][c] = 0.f;
#pragma unroll
        for (int a = 0; a < 8; a++)
#pragma unroll
            for (int c = 0; c < 4; c++) Sr[a][c] = 0.f;

#pragma unroll
        for (int k16 = 0; k16 < 4; k16++) {
            int kb = k16 * 32 + hf * 16;
            uint32_t aqh[4], aql[4];
            uint32_t swA = SW128((wm * 16 + rl) * 128 + kb);
            LDSM4(aqh, sQh + swA);
            LDSM4(aql, sQl + swA);
            uint32_t bkh[2][4], bkl[2][4];
#pragma unroll
            for (int nt = 0; nt < 2; nt++) {
                uint32_t sw = SW128((wn * 32 + nt * 16 + rl) * 128 + kb);
                LDSM4(bkh[nt], st + sw);
                LDSM4(bkl[nt], st + 8192 + sw);
            }
#pragma unroll
            for (int n8 = 0; n8 < 4; n8++) {
                int nt = n8 >> 1, sl = n8 & 1;
                MMA16816(Sc[n8], aqh, bkh[nt][sl], bkh[nt][sl + 2]);
                MMA16816(Sc[n8], aql, bkh[nt][sl], bkh[nt][sl + 2]);
                MMA16816(Sc[n8], aqh, bkl[nt][sl], bkl[nt][sl + 2]);
            }
            uint32_t beh[4][4], bel[4][4];
#pragma unroll
            for (int nt = 0; nt < 4; nt++) {
                uint32_t sw = SW128((wn * 64 + nt * 16 + rl) * 128 + kb);
                LDSM4(beh[nt], st + 32768 + sw);
                LDSM4(bel[nt], st + 49152 + sw);
            }
#pragma unroll
            for (int n8 = 0; n8 < 8; n8++) {
                int nt = n8 >> 1, sl = n8 & 1;
                MMA16816(Sr[n8], aqh, beh[nt][sl], beh[nt][sl + 2]);
                MMA16816(Sr[n8], aql, beh[nt][sl], beh[nt][sl + 2]);
                MMA16816(Sr[n8], aqh, bel[nt][sl], bel[nt][sl + 2]);
            }
        }

        // ---- stage rel to SMEM (fp32 [64][132])
        {
            int i0 = wm * 16 + r4;
#pragma unroll
            for (int n8 = 0; n8 < 8; n8++) {
                int u = wn * 64 + n8 * 8 + c2;
                *(float2*)(Rsm + (size_t)i0 * 132 + u)       = make_float2(Sr[n8][0], Sr[n8][1]);
                *(float2*)(Rsm + (size_t)(i0 + 8) * 132 + u) = make_float2(Sr[n8][2], Sr[n8][3]);
            }
        }
        __syncthreads();

        // ---- gather rel diagonal band + scale + causal mask
        const bool diag = (it == nit - 1);
        int i0 = wm * 16 + r4, i1 = i0 + 8;
#pragma unroll
        for (int n8 = 0; n8 < 4; n8++) {
            int j = wn * 32 + n8 * 8 + c2;
            Sc[n8][0] = (Sc[n8][0] + Rsm[(size_t)i0 * 132 + (j     - i0 + 63)]) * 0.125f;
            Sc[n8][1] = (Sc[n8][1] + Rsm[(size_t)i0 * 132 + (j + 1 - i0 + 63)]) * 0.125f;
            Sc[n8][2] = (Sc[n8][2] + Rsm[(size_t)i1 * 132 + (j     - i1 + 63)]) * 0.125f;
            Sc[n8][3] = (Sc[n8][3] + Rsm[(size_t)i1 * 132 + (j + 1 - i1 + 63)]) * 0.125f;
            if (diag) {
                if (j     > i0) Sc[n8][0] = -1.0e30f;
                if (j + 1 > i0) Sc[n8][1] = -1.0e30f;
                if (j     > i1) Sc[n8][2] = -1.0e30f;
                if (j + 1 > i1) Sc[n8][3] = -1.0e30f;
            }
        }

        // ---- row max (quad shuffle + cross-warp SMEM exchange)
        float m0_ = -3.0e38f, m1_ = -3.0e38f;
#pragma unroll
        for (int n8 = 0; n8 < 4; n8++) {
            m0_ = fmaxf(m0_, fmaxf(Sc[n8][0], Sc[n8][1]));
            m1_ = fmaxf(m1_, fmaxf(Sc[n8][2], Sc[n8][3]));
        }
        m0_ = fmaxf(m0_, __shfl_xor_sync(0xffffffffu, m0_, 1));
        m0_ = fmaxf(m0_, __shfl_xor_sync(0xffffffffu, m0_, 2));
        m1_ = fmaxf(m1_, __shfl_xor_sync(0xffffffffu, m1_, 1));
        m1_ = fmaxf(m1_, __shfl_xor_sync(0xffffffffu, m1_, 2));
        if ((lane & 3) == 0) {
            redA[i0 * 2 + wn] = m0_;
            redA[i1 * 2 + wn] = m1_;
        }
        __syncthreads();
        m0_ = fmaxf(redA[i0 * 2], redA[i0 * 2 + 1]);
        m1_ = fmaxf(redA[i1 * 2], redA[i1 * 2 + 1]);

        float mn0 = fmaxf(Mx[0], m0_), mn1 = fmaxf(Mx[1], m1_);
        float al0 = __expf(Mx[0] - mn0), al1 = __expf(Mx[1] - mn1);

        // ---- exp + row sum
        float s0 = 0.f, s1 = 0.f;
#pragma unroll
        for (int n8 = 0; n8 < 4; n8++) {
            Sc[n8][0] = __expf(Sc[n8][0] - mn0);
            Sc[n8][1] = __expf(Sc[n8][1] - mn0);
            Sc[n8][2] = __expf(Sc[n8][2] - mn1);
            Sc[n8][3] = __expf(Sc[n8][3] - mn1);
            s0 += Sc[n8][0] + Sc[n8][1];
            s1 += Sc[n8][2] + Sc[n8][3];
        }
        s0 += __shfl_xor_sync(0xffffffffu, s0, 1);
        s0 += __shfl_xor_sync(0xffffffffu, s0, 2);
        s1 += __shfl_xor_sync(0xffffffffu, s1, 1);
        s1 += __shfl_xor_sync(0xffffffffu, s1, 2);
        if ((lane & 3) == 0) {
            redB[i0 * 2 + wn] = s0;
            redB[i1 * 2 + wn] = s1;
        }
        __syncthreads();
        s0 = redB[i0 * 2] + redB[i0 * 2 + 1];
        s1 = redB[i1 * 2] + redB[i1 * 2 + 1];

        Lx[0] = Lx[0] * al0 + s0; Mx[0] = mn0;
        Lx[1] = Lx[1] * al1 + s1; Mx[1] = mn1;
#pragma unroll
        for (int n8 = 0; n8 < 4; n8++) {
            O[n8][0] *= al0; O[n8][1] *= al0;
            O[n8][2] *= al1; O[n8][3] *= al1;
        }

        // ---- P -> SMEM (bf16 split, swizzled rows i x 64 cols)
#pragma unroll
        for (int n8 = 0; n8 < 4; n8++) {
            int jb = (wn * 32 + n8 * 8 + c2) * 2;   // byte col offset
            uint32_t h01, l01, h23, l23;
            split2(Sc[n8][0], Sc[n8][1], h01, l01);
            split2(Sc[n8][2], Sc[n8][3], h23, l23);
            uint32_t o0 = SW128(i0 * 128 + jb), o1 = SW128(i1 * 128 + jb);
            *(uint32_t*)(smem + 181248 + o0) = h01;
            *(uint32_t*)(smem + 189440 + o0) = l01;
            *(uint32_t*)(smem + 181248 + o1) = h23;
            *(uint32_t*)(smem + 189440 + o1) = l23;
        }
        __syncthreads();

        // ---- P @ V^T  (A = P rows, B = Vt rows d, k = keys)
#pragma unroll
        for (int k16 = 0; k16 < 4; k16++) {
            int kb = k16 * 32 + hf * 16;
            uint32_t aph[4], apl[4];
            uint32_t swA = SW128((wm * 16 + rl) * 128 + kb);
            LDSM4(aph, sb + 181248 + swA);
            LDSM4(apl, sb + 189440 + swA);
            uint32_t bvh[2][4], bvl[2][4];
#pragma unroll
            for (int nt = 0; nt < 2; nt++) {
                uint32_t sw = SW128((wn * 32 + nt * 16 + rl) * 128 + kb);
                LDSM4(bvh[nt], st + 16384 + sw);
                LDSM4(bvl[nt], st + 24576 + sw);
            }
#pragma unroll
            for (int n8 = 0; n8 < 4; n8++) {
                int nt = n8 >> 1, sl = n8 & 1;
                MMA16816(O[n8], aph, bvh[nt][sl], bvh[nt][sl + 2]);
                MMA16816(O[n8], apl, bvh[nt][sl], bvh[nt][sl + 2]);
                MMA16816(O[n8], aph, bvl[nt][sl], bvl[nt][sl + 2]);
            }
        }
        __syncthreads();   // protect stage/P/R reuse next iteration
    }

    // ---- normalize + FUSED split write: g_ah/g_al[b][n0+i][h*64 + col]
    {
        int b = bh >> 4, h = bh & 15;
        float inv0 = 1.0f / Lx[0], inv1 = 1.0f / Lx[1];
        size_t opb = ((size_t)(b * 1024) + n0) * 1024 + h * 64;
        int i0 = wm * 16 + r4;
#pragma unroll
        for (int n8 = 0; n8 < 4; n8++) {
            int col = wn * 32 + n8 * 8 + c2;
            uint32_t hh, ll;
            split2(O[n8][0] * inv0, O[n8][1] * inv0, hh, ll);
            *(uint32_t*)(g_ah + opb + (size_t)i0 * 1024 + col) = hh;
            *(uint32_t*)(g_al + opb + (size_t)i0 * 1024 + col) = ll;
            split2(O[n8][2] * inv1, O[n8][3] * inv1, hh, ll);
            *(uint32_t*)(g_ah + opb + (size_t)(i0 + 8) * 1024 + col) = hh;
            *(uint32_t*)(g_al + opb + (size_t)(i0 + 8) * 1024 + col) = ll;
        }
    }
}

// ---------------------------------------------------------------------------
extern "C" void kernel_launch(void* const* d_in, const int* in_sizes, int n_in,
                              void* d_out, int out_size)
{
    const float* x      = (const float*)d_in[0];
    const float* W_qkv  = (const float*)d_in[1];
    const float* W_proj = (const float*)d_in[2];
    const float* b_proj = (const float*)d_in[3];
    const float* Er     = (const float*)d_in[4];
    float* out = (float*)d_out;

    __nv_bfloat16 *ah, *al, *wh, *wl, *ph, *pl, *erh, *erl;
    cudaGetSymbolAddress((void**)&ah, g_ah);
    cudaGetSymbolAddress((void**)&al, g_al);
    cudaGetSymbolAddress((void**)&wh, g_wh);
    cudaGetSymbolAddress((void**)&wl, g_wl);
    cudaGetSymbolAddress((void**)&ph, g_ph);
    cudaGetSymbolAddress((void**)&pl, g_pl);
    cudaGetSymbolAddress((void**)&erh, g_erh);
    cudaGetSymbolAddress((void**)&erl, g_erl);

    int gemm_smem = 2 * STAGE_;   // 128 KB
    cudaFuncSetAttribute(gemm_qkv,  cudaFuncAttributeMaxDynamicSharedMemorySize, gemm_smem);
    cudaFuncSetAttribute(gemm_proj, cudaFuncAttributeMaxDynamicSharedMemorySize, gemm_smem);
    cudaFuncSetAttribute(attn_mma,  cudaFuncAttributeMaxDynamicSharedMemorySize, ASMEM_);

    int n_x  = ROWS_ * DIM_;
    int n_wq = 3 * DIM_ * DIM_;
    int n_wp = DIM_ * DIM_;

    split_bf16<<<n_x  / 1024, 256>>>(x,      ah, al, n_x);
    split_bf16<<<n_wq / 1024, 256>>>(W_qkv,  wh, wl, n_wq);
    split_bf16<<<n_wp / 1024, 256>>>(W_proj, ph, pl, n_wp);
    split_bf16<<<64, 256>>>(Er, erh, erl, 1024 * 64);

    // 1) QKV projection with fused head-split epilogue
    gemm_qkv<<<dim3(3 * DIM_ / 128, ROWS_ / 128), 512, gemm_smem>>>(
        ah, al, wh, wl, DIM_);

    // 2) tensor-core attention (writes split attn-out to g_ah/g_al)
    attn_mma<<<dim3(16, 64), 256, ASMEM_>>>();

    // 3) output projection + bias
    gemm_proj<<<dim3(DIM_ / 128, ROWS_ / 128), 512, gemm_smem>>>(
        ah, al, ph, pl, b_proj, out, ROWS_, DIM_, DIM_);
}